// round 1
// baseline (speedup 1.0000x reference)
#include <cuda_runtime.h>
#include <cstddef>

// LstmTl: N=64, L=128, D=H=64, 3 gates.
// Phase 1: xg[l,g,n,a,b] = sum_{i,j} x[n,l,i,j] * Ww1[g,a,i] * Ww2[g,b,j]
// Phase 2: per n (one CTA), loop t: hg[g]=Wu1[g]@h@Wu2[g]^T; gates; update c,h.

#define NBATCH 64
#define LSTEPS 128
#define DIM    64

// xg scratch: L * 3 * N * 64 * 64 floats = 100,663,296 floats (402 MB)
__device__ float g_xg[(size_t)LSTEPS * 3 * NBATCH * DIM * DIM];

__device__ __forceinline__ float sigm(float x) {
    return 1.0f / (1.0f + __expf(-x));
}

// ---------------------------------------------------------------------------
// Phase 1: one CTA per (l, n, g). 256 threads, 4x4 register tiles.
// smem: xs[64][64] (i,j) | W1t[64][64] (i,a) | W2t[64][68] (j,b) | ts[64][68] (j,a)
// ---------------------------------------------------------------------------
__global__ void __launch_bounds__(256) phase1_kernel(
    const float* __restrict__ x,     // (N, L, 64, 64)
    const float* __restrict__ Ww1,   // (4, 64, 64) g,a,i
    const float* __restrict__ Ww2,   // (4, 64, 64) g,b,j
    float* __restrict__ xg)          // (L, 3, N, 64, 64)
{
    extern __shared__ float sm[];
    float* xs  = sm;                  // 4096
    float* W1t = sm + 4096;           // 4096  [i][a]
    float* W2t = sm + 8192;           // 64*68 [j][b]
    float* ts  = sm + 8192 + 64 * 68; // 64*68 [j][a]

    const int tid = threadIdx.x;
    const int g = blockIdx.y;
    const int l = blockIdx.x >> 6;
    const int n = blockIdx.x & 63;

    // load x[n,l] (16KB) as float4
    {
        const float4* src = (const float4*)(x + ((size_t)(n * LSTEPS + l)) * 4096);
        float4* dst = (float4*)xs;
        #pragma unroll
        for (int k = 0; k < 4; k++) dst[tid + 256 * k] = src[tid + 256 * k];
    }
    // load Ww1[g] transposed -> [i][a]
    {
        const float* w = Ww1 + g * 4096;
        #pragma unroll
        for (int k = 0; k < 16; k++) {
            int e = tid + 256 * k;
            int a = e >> 6, i = e & 63;
            W1t[i * 64 + a] = w[e];
        }
    }
    // load Ww2[g] transposed -> [j][b], padded row 68
    {
        const float* w = Ww2 + g * 4096;
        #pragma unroll
        for (int k = 0; k < 16; k++) {
            int e = tid + 256 * k;
            int b = e >> 6, j = e & 63;
            W2t[j * 68 + b] = w[e];
        }
    }
    __syncthreads();

    const int ty = tid >> 4, tx = tid & 15;
    const int a0 = ty * 4, j0 = tx * 4, b0 = tx * 4;

    // matmul1: t[a][j] = sum_i W1[a][i] * x[i][j]
    float acc[4][4];
    #pragma unroll
    for (int aa = 0; aa < 4; aa++)
        #pragma unroll
        for (int jj = 0; jj < 4; jj++) acc[aa][jj] = 0.0f;

    #pragma unroll 8
    for (int i = 0; i < 64; i++) {
        float4 av = *(const float4*)(W1t + i * 64 + a0);
        float4 xv = *(const float4*)(xs + i * 64 + j0);
        float a_[4] = {av.x, av.y, av.z, av.w};
        float x_[4] = {xv.x, xv.y, xv.z, xv.w};
        #pragma unroll
        for (int aa = 0; aa < 4; aa++)
            #pragma unroll
            for (int jj = 0; jj < 4; jj++)
                acc[aa][jj] = fmaf(a_[aa], x_[jj], acc[aa][jj]);
    }
    // write transposed ts[j][a]
    #pragma unroll
    for (int jj = 0; jj < 4; jj++) {
        float4 v = make_float4(acc[0][jj], acc[1][jj], acc[2][jj], acc[3][jj]);
        *(float4*)(ts + (j0 + jj) * 68 + a0) = v;
    }
    __syncthreads();

    // matmul2: xg[a][b] = sum_j t[a][j] * W2[b][j]
    float acc2[4][4];
    #pragma unroll
    for (int aa = 0; aa < 4; aa++)
        #pragma unroll
        for (int bb = 0; bb < 4; bb++) acc2[aa][bb] = 0.0f;

    #pragma unroll 8
    for (int j = 0; j < 64; j++) {
        float4 tv = *(const float4*)(ts + j * 68 + a0);
        float4 wv = *(const float4*)(W2t + j * 68 + b0);
        float t_[4] = {tv.x, tv.y, tv.z, tv.w};
        float w_[4] = {wv.x, wv.y, wv.z, wv.w};
        #pragma unroll
        for (int aa = 0; aa < 4; aa++)
            #pragma unroll
            for (int bb = 0; bb < 4; bb++)
                acc2[aa][bb] = fmaf(t_[aa], w_[bb], acc2[aa][bb]);
    }

    float* dst = xg + ((size_t)((l * 3 + g) * NBATCH + n)) * 4096;
    #pragma unroll
    for (int aa = 0; aa < 4; aa++) {
        float4 v = make_float4(acc2[aa][0], acc2[aa][1], acc2[aa][2], acc2[aa][3]);
        *(float4*)(dst + (a0 + aa) * 64 + b0) = v;
    }
}

// ---------------------------------------------------------------------------
// Phase 2: one CTA per n. 256 threads. t-loop in kernel, h in smem, c in regs.
// smem: hs[64][64] | W1t[3][64][64] (g,i,a) | W2t[3][64][68] (g,j,b) | ts[64][68]
// ---------------------------------------------------------------------------
__global__ void __launch_bounds__(256, 1) phase2_kernel(
    const float* __restrict__ Wu1,   // (4,64,64) g,a,i
    const float* __restrict__ Wu2,   // (4,64,64) g,b,j
    const float* __restrict__ xg,    // (L,3,N,64,64)
    float* __restrict__ out)         // outs | h_last | c_last
{
    extern __shared__ float sm[];
    float* hs  = sm;                          // 4096         [i][j]
    float* W1t = sm + 4096;                   // 3*4096       [g][i][a]
    float* W2t = sm + 4096 + 3 * 4096;        // 3*64*68      [g][j][b]
    float* ts  = sm + 4096 + 3 * 4096 + 3 * 64 * 68; // 64*68 [j][a]

    const int tid = threadIdx.x;
    const int n = blockIdx.x;

    // load Wu1[0..2] transposed
    #pragma unroll
    for (int k = 0; k < 48; k++) {
        int e = tid + 256 * k;            // e < 12288
        int g = e >> 12, r = e & 4095;
        int a = r >> 6, i = r & 63;
        W1t[(g * 64 + i) * 64 + a] = Wu1[e];
    }
    #pragma unroll
    for (int k = 0; k < 48; k++) {
        int e = tid + 256 * k;
        int g = e >> 12, r = e & 4095;
        int b = r >> 6, j = r & 63;
        W2t[(g * 64 + j) * 68 + b] = Wu2[e];
    }
    // zero h
    #pragma unroll
    for (int k = 0; k < 16; k++) hs[tid + 256 * k] = 0.0f;

    const int ty = tid >> 4, tx = tid & 15;
    const int a0 = ty * 4, j0 = tx * 4, b0 = tx * 4;

    float c[4][4];
    #pragma unroll
    for (int aa = 0; aa < 4; aa++)
        #pragma unroll
        for (int bb = 0; bb < 4; bb++) c[aa][bb] = 0.0f;

    float gt[3][4][4];

    for (int t = 0; t < LSTEPS; t++) {
        #pragma unroll 1
        for (int g = 0; g < 3; g++) {
            __syncthreads();   // hs stable / previous ts consumers done

            // matmul1: tmp[a][j] = sum_i Wu1[g][a][i] * h[i][j]
            float acc[4][4];
            #pragma unroll
            for (int aa = 0; aa < 4; aa++)
                #pragma unroll
                for (int jj = 0; jj < 4; jj++) acc[aa][jj] = 0.0f;

            const float* w1 = W1t + g * 4096;
            #pragma unroll 8
            for (int i = 0; i < 64; i++) {
                float4 av = *(const float4*)(w1 + i * 64 + a0);
                float4 hv = *(const float4*)(hs + i * 64 + j0);
                float a_[4] = {av.x, av.y, av.z, av.w};
                float h_[4] = {hv.x, hv.y, hv.z, hv.w};
                #pragma unroll
                for (int aa = 0; aa < 4; aa++)
                    #pragma unroll
                    for (int jj = 0; jj < 4; jj++)
                        acc[aa][jj] = fmaf(a_[aa], h_[jj], acc[aa][jj]);
            }
            #pragma unroll
            for (int jj = 0; jj < 4; jj++) {
                float4 v = make_float4(acc[0][jj], acc[1][jj], acc[2][jj], acc[3][jj]);
                *(float4*)(ts + (j0 + jj) * 68 + a0) = v;
            }
            __syncthreads();   // ts ready

            // matmul2: hg[a][b] = sum_j tmp[a][j] * Wu2[g][b][j]; add xg; sigmoid
            float acc2[4][4];
            #pragma unroll
            for (int aa = 0; aa < 4; aa++)
                #pragma unroll
                for (int bb = 0; bb < 4; bb++) acc2[aa][bb] = 0.0f;

            const float* w2 = W2t + g * 64 * 68;
            #pragma unroll 8
            for (int j = 0; j < 64; j++) {
                float4 tv = *(const float4*)(ts + j * 68 + a0);
                float4 wv = *(const float4*)(w2 + j * 68 + b0);
                float t_[4] = {tv.x, tv.y, tv.z, tv.w};
                float w_[4] = {wv.x, wv.y, wv.z, wv.w};
                #pragma unroll
                for (int aa = 0; aa < 4; aa++)
                    #pragma unroll
                    for (int bb = 0; bb < 4; bb++)
                        acc2[aa][bb] = fmaf(t_[aa], w_[bb], acc2[aa][bb]);
            }

            const float* xgp = xg + ((size_t)((t * 3 + g) * NBATCH + n)) * 4096;
            #pragma unroll
            for (int aa = 0; aa < 4; aa++) {
                float4 xv = *(const float4*)(xgp + (a0 + aa) * 64 + b0);
                gt[g][aa][0] = sigm(acc2[aa][0] + xv.x);
                gt[g][aa][1] = sigm(acc2[aa][1] + xv.y);
                gt[g][aa][2] = sigm(acc2[aa][2] + xv.z);
                gt[g][aa][3] = sigm(acc2[aa][3] + xv.w);
            }
        }

        // epilogue: c = r*(c+z); h = o*sigmoid(c)
        float* od = out + ((size_t)(n * LSTEPS + t)) * 4096;
        #pragma unroll
        for (int aa = 0; aa < 4; aa++) {
            float hvals[4];
            #pragma unroll
            for (int bb = 0; bb < 4; bb++) {
                float z = gt[0][aa][bb];
                float r = gt[1][aa][bb];
                float o = gt[2][aa][bb];
                c[aa][bb] = r * (c[aa][bb] + z);
                hvals[bb] = o * sigm(c[aa][bb]);
            }
            float4 hv4 = make_float4(hvals[0], hvals[1], hvals[2], hvals[3]);
            *(float4*)(od + (a0 + aa) * 64 + b0) = hv4;            // outs
            *(float4*)(hs + (a0 + aa) * 64 + b0) = hv4;            // state for next step
        }
        // next iteration's first __syncthreads() publishes hs
    }

    __syncthreads();
    // h_last
    {
        float* hl = out + (size_t)NBATCH * LSTEPS * 4096 + (size_t)n * 4096;
        #pragma unroll
        for (int k = 0; k < 16; k++) hl[tid + 256 * k] = hs[tid + 256 * k];
    }
    // c_last (from registers)
    {
        float* cl = out + (size_t)NBATCH * LSTEPS * 4096 + (size_t)NBATCH * 4096
                        + (size_t)n * 4096;
        #pragma unroll
        for (int aa = 0; aa < 4; aa++) {
            float4 v = make_float4(c[aa][0], c[aa][1], c[aa][2], c[aa][3]);
            *(float4*)(cl + (a0 + aa) * 64 + b0) = v;
        }
    }
}

// ---------------------------------------------------------------------------

extern "C" void kernel_launch(void* const* d_in, const int* in_sizes, int n_in,
                              void* d_out, int out_size)
{
    const float* x   = (const float*)d_in[0];
    const float* Ww1 = (const float*)d_in[1];
    const float* Ww2 = (const float*)d_in[2];
    const float* Wu1 = (const float*)d_in[3];
    const float* Wu2 = (const float*)d_in[4];
    float* out = (float*)d_out;

    float* xg = nullptr;
    cudaGetSymbolAddress((void**)&xg, g_xg);

    const size_t smem1 = (4096 + 4096 + 64 * 68 + 64 * 68) * sizeof(float);        // 67584
    const size_t smem2 = (4096 + 3 * 4096 + 3 * 64 * 68 + 64 * 68) * sizeof(float); // 135168

    cudaFuncSetAttribute(phase1_kernel, cudaFuncAttributeMaxDynamicSharedMemorySize, (int)smem1);
    cudaFuncSetAttribute(phase2_kernel, cudaFuncAttributeMaxDynamicSharedMemorySize, (int)smem2);

    dim3 grid1(LSTEPS * NBATCH, 3);
    phase1_kernel<<<grid1, 256, smem1>>>(x, Ww1, Ww2, xg);
    phase2_kernel<<<NBATCH, 256, smem2>>>(Wu1, Wu2, xg, out);
}

// round 2
// speedup vs baseline: 1.5625x; 1.5625x over previous
#include <cuda_runtime.h>
#include <cstdint>
#include <cstddef>

// LstmTl: N=64, L=128, D=H=64, 3 gates.
// Phase 1: xg[l,g,n,a,b] = sum_{i,j} x[n,l,i,j] * Ww1[g,a,i] * Ww2[g,b,j]
//          one CTA per (n,l), 192 threads = 3 gate-groups of 64, 8x8 reg tiles.
// Phase 2: cluster of 2 CTAs per n; each CTA owns 32 a-rows of all 3 gates.
//          h halves exchanged via DSMEM stores + cluster barriers.

#define NB 64
#define LS 128

__device__ float g_xg[(size_t)LS * 3 * NB * 4096];

__device__ __forceinline__ float sigm(float x) {
    return 1.0f / (1.0f + __expf(-x));
}

// ---------------------------------------------------------------------------
// Phase 1
// smem: xs[64][64] | W1t[3][64][68] (g,i,a) | W2t[3][64][68] (g,j,b) | ts[3][64][68] (g,j,a)
// ---------------------------------------------------------------------------
__global__ void __launch_bounds__(192, 1) phase1_kernel(
    const float* __restrict__ x,     // (N, L, 64, 64)
    const float* __restrict__ Ww1,   // (4, 64, 64) g,a,i
    const float* __restrict__ Ww2,   // (4, 64, 64) g,b,j
    float* __restrict__ xg)          // (L, 3, N, 64, 64)
{
    extern __shared__ float sm[];
    float* xs  = sm;                    // 4096
    float* W1t = sm + 4096;             // 3*64*68
    float* W2t = W1t + 3 * 64 * 68;     // 3*64*68
    float* ts  = W2t + 3 * 64 * 68;     // 3*64*68

    const int tid = threadIdx.x;
    const int n = blockIdx.x >> 7;
    const int l = blockIdx.x & 127;

    // load x[n,l] (16KB)
    {
        const float4* src = (const float4*)(x + ((size_t)(n * LS + l)) * 4096);
        #pragma unroll
        for (int k = 0; k < 6; k++) {
            int idx = tid + 192 * k;
            if (idx < 1024) ((float4*)xs)[idx] = src[idx];
        }
    }
    // load + transpose weights (3 gates each)
    #pragma unroll
    for (int k = 0; k < 16; k++) {
        int e4 = tid + 192 * k;                 // 0..3071
        float4 v1 = ((const float4*)Ww1)[e4];
        float4 v2 = ((const float4*)Ww2)[e4];
        int e = e4 * 4;
        int g = e >> 12, r = e & 4095;
        int row = r >> 6, col = r & 63;         // Ww1: row=a, col=i ; Ww2: row=b, col=j
        float* p1 = W1t + (g * 64 + col) * 68 + row;
        p1[0] = v1.x; p1[68] = v1.y; p1[136] = v1.z; p1[204] = v1.w;
        float* p2 = W2t + (g * 64 + col) * 68 + row;
        p2[0] = v2.x; p2[68] = v2.y; p2[136] = v2.z; p2[204] = v2.w;
    }
    __syncthreads();

    const int g  = tid >> 6;          // gate 0..2
    const int q  = tid & 63;
    const int a0 = (q >> 3) * 8;
    const int j0 = (q & 7) * 8;

    // stage1: tmp[a][j] = sum_i W1[a][i] * x[i][j]   (store transposed ts[j][a])
    float acc[8][8];
    #pragma unroll
    for (int aa = 0; aa < 8; aa++)
        #pragma unroll
        for (int jj = 0; jj < 8; jj++) acc[aa][jj] = 0.0f;

    const float* w1 = W1t + g * 64 * 68;
    #pragma unroll 4
    for (int i = 0; i < 64; i++) {
        float4 wA = *(const float4*)(w1 + i * 68 + a0);
        float4 wB = *(const float4*)(w1 + i * 68 + a0 + 4);
        float4 xA = *(const float4*)(xs + i * 64 + j0);
        float4 xB = *(const float4*)(xs + i * 64 + j0 + 4);
        float wa[8] = {wA.x, wA.y, wA.z, wA.w, wB.x, wB.y, wB.z, wB.w};
        float xv[8] = {xA.x, xA.y, xA.z, xA.w, xB.x, xB.y, xB.z, xB.w};
        #pragma unroll
        for (int aa = 0; aa < 8; aa++)
            #pragma unroll
            for (int jj = 0; jj < 8; jj++)
                acc[aa][jj] = fmaf(wa[aa], xv[jj], acc[aa][jj]);
    }
    float* tsg = ts + g * 64 * 68;
    #pragma unroll
    for (int jj = 0; jj < 8; jj++) {
        *(float4*)(tsg + (j0 + jj) * 68 + a0) =
            make_float4(acc[0][jj], acc[1][jj], acc[2][jj], acc[3][jj]);
        *(float4*)(tsg + (j0 + jj) * 68 + a0 + 4) =
            make_float4(acc[4][jj], acc[5][jj], acc[6][jj], acc[7][jj]);
    }
    __syncthreads();

    // stage2: xg[a][b] = sum_j ts[j][a] * W2[b][j]
    const int b0 = j0;
    float acc2[8][8];
    #pragma unroll
    for (int aa = 0; aa < 8; aa++)
        #pragma unroll
        for (int bb = 0; bb < 8; bb++) acc2[aa][bb] = 0.0f;

    const float* w2 = W2t + g * 64 * 68;
    #pragma unroll 4
    for (int j = 0; j < 64; j++) {
        float4 tA = *(const float4*)(tsg + j * 68 + a0);
        float4 tB = *(const float4*)(tsg + j * 68 + a0 + 4);
        float4 wA = *(const float4*)(w2 + j * 68 + b0);
        float4 wB = *(const float4*)(w2 + j * 68 + b0 + 4);
        float ta[8] = {tA.x, tA.y, tA.z, tA.w, tB.x, tB.y, tB.z, tB.w};
        float wb[8] = {wA.x, wA.y, wA.z, wA.w, wB.x, wB.y, wB.z, wB.w};
        #pragma unroll
        for (int aa = 0; aa < 8; aa++)
            #pragma unroll
            for (int bb = 0; bb < 8; bb++)
                acc2[aa][bb] = fmaf(ta[aa], wb[bb], acc2[aa][bb]);
    }
    float* dst = xg + ((size_t)((l * 3 + g) * NB + n)) * 4096;
    #pragma unroll
    for (int aa = 0; aa < 8; aa++) {
        *(float4*)(dst + (a0 + aa) * 64 + b0) =
            make_float4(acc2[aa][0], acc2[aa][1], acc2[aa][2], acc2[aa][3]);
        *(float4*)(dst + (a0 + aa) * 64 + b0 + 4) =
            make_float4(acc2[aa][4], acc2[aa][5], acc2[aa][6], acc2[aa][7]);
    }
}

// ---------------------------------------------------------------------------
// Phase 2: grid 128 = 2 per n, cluster (2,1,1), 256 threads.
// CTA rank r owns a-rows [32r, 32r+32) of all gates; full h replicated in both.
// smem: hs[64][64] | W1t[3][64][36] | W2t[3][64][68] | ts[3][64][36] |
//       hg[3][32][64] | xgs[3][32][64]
// ---------------------------------------------------------------------------
__global__ void __launch_bounds__(256, 1) __cluster_dims__(2, 1, 1) phase2_kernel(
    const float* __restrict__ Wu1,   // (4,64,64) g,a,i
    const float* __restrict__ Wu2,   // (4,64,64) g,b,j
    const float* __restrict__ xg,    // (L,3,N,64,64)
    float* __restrict__ out)         // outs | h_last | c_last
{
    extern __shared__ float sm[];
    float* hs  = sm;                 // 4096
    float* W1t = sm + 4096;          // 3*64*36 = 6912  [g][i][a_loc]
    float* W2t = W1t + 6912;         // 3*64*68 = 13056 [g][j][b]
    float* ts  = W2t + 13056;        // 3*64*36 = 6912  [g][j][a_loc]
    float* hgv = ts + 6912;          // 3*32*64 = 6144
    float* xgs = hgv + 6144;         // 6144

    const int tid = threadIdx.x;
    uint32_t rk;
    asm("mov.u32 %0, %%cluster_ctarank;" : "=r"(rk));
    const int n  = blockIdx.x >> 1;
    const int A0 = (int)rk * 32;

    // W1t[g][i][al] = Wu1[g][A0+al][i]
    #pragma unroll
    for (int k = 0; k < 24; k++) {
        int idx = tid + 256 * k;                 // < 6144
        int g = idx / 2048, rem = idx & 2047;
        int al = rem >> 6, i = rem & 63;
        W1t[(g * 64 + i) * 36 + al] = Wu1[g * 4096 + (A0 + al) * 64 + i];
    }
    // W2t[g][j][b] = Wu2[g][b][j]
    #pragma unroll
    for (int k = 0; k < 48; k++) {
        int idx = tid + 256 * k;                 // < 12288
        int g = idx >> 12, rem = idx & 4095;
        int b = rem >> 6, j = rem & 63;
        W2t[(g * 64 + j) * 68 + b] = Wu2[idx];
    }
    #pragma unroll
    for (int k = 0; k < 16; k++) hs[tid + 256 * k] = 0.0f;

    uint32_t hs_local = (uint32_t)__cvta_generic_to_shared(hs);
    uint32_t hs_peer;
    asm("mapa.shared::cluster.u32 %0, %1, %2;"
        : "=r"(hs_peer) : "r"(hs_local), "r"(rk ^ 1u));

    const int gg = tid >> 6;          // 0..2 matmul groups, 3 = cp.async group
    const int q  = tid & 63;
    const int a0 = (q >> 3) * 4;      // a_loc tile base (stage1/2)
    const int j0 = (q & 7) * 8;       // j / b tile base
    const int e_al = tid >> 3;        // epilogue row 0..31
    const int e_b0 = (tid & 7) * 8;

    float c[8];
    #pragma unroll
    for (int k = 0; k < 8; k++) c[k] = 0.0f;

    __syncthreads();
    asm volatile("barrier.cluster.arrive.aligned;" ::: "memory");
    asm volatile("barrier.cluster.wait.aligned;" ::: "memory");

    for (int t = 0; t < LS; t++) {
        if (gg == 3) {
            // prefetch xg slab for this step: 3 gates x 32 rows x 256B
            #pragma unroll
            for (int k = 0; k < 24; k++) {
                int cc = q + 64 * k;                      // < 1536 16B-chunks
                int gx = cc >> 9, rem = cc & 511;
                int row = rem >> 4, off = rem & 15;
                const float* src = xg + ((size_t)((t * 3 + gx) * NB + n)) * 4096
                                      + (A0 + row) * 64 + off * 4;
                uint32_t dsts = (uint32_t)__cvta_generic_to_shared(
                    xgs + gx * 2048 + row * 64 + off * 4);
                asm volatile("cp.async.ca.shared.global [%0], [%1], 16;"
                             :: "r"(dsts), "l"(src));
            }
            asm volatile("cp.async.commit_group;");
        } else {
            // stage1: ts[g][j][al] = sum_i W1t[g][i][al] * hs[i][j]
            float acc[4][8];
            #pragma unroll
            for (int aa = 0; aa < 4; aa++)
                #pragma unroll
                for (int jj = 0; jj < 8; jj++) acc[aa][jj] = 0.0f;
            const float* w1 = W1t + gg * 64 * 36;
            #pragma unroll 4
            for (int i = 0; i < 64; i++) {
                float4 wv = *(const float4*)(w1 + i * 36 + a0);
                float4 hA = *(const float4*)(hs + i * 64 + j0);
                float4 hB = *(const float4*)(hs + i * 64 + j0 + 4);
                float wa[4] = {wv.x, wv.y, wv.z, wv.w};
                float hv[8] = {hA.x, hA.y, hA.z, hA.w, hB.x, hB.y, hB.z, hB.w};
                #pragma unroll
                for (int aa = 0; aa < 4; aa++)
                    #pragma unroll
                    for (int jj = 0; jj < 8; jj++)
                        acc[aa][jj] = fmaf(wa[aa], hv[jj], acc[aa][jj]);
            }
            float* tg = ts + gg * 64 * 36;
            #pragma unroll
            for (int jj = 0; jj < 8; jj++)
                *(float4*)(tg + (j0 + jj) * 36 + a0) =
                    make_float4(acc[0][jj], acc[1][jj], acc[2][jj], acc[3][jj]);
        }
        __syncthreads();
        // my CTA is done reading hs for this step
        asm volatile("barrier.cluster.arrive.aligned;" ::: "memory");

        if (gg < 3) {
            // stage2: hg[al][b] = sum_j ts[g][j][al] * W2t[g][j][b]
            float acc2[4][8];
            #pragma unroll
            for (int aa = 0; aa < 4; aa++)
                #pragma unroll
                for (int bb = 0; bb < 8; bb++) acc2[aa][bb] = 0.0f;
            const float* w2 = W2t + gg * 64 * 68;
            const float* tg = ts + gg * 64 * 36;
            #pragma unroll 4
            for (int j = 0; j < 64; j++) {
                float4 tv = *(const float4*)(tg + j * 36 + a0);
                float4 wA = *(const float4*)(w2 + j * 68 + j0);
                float4 wB = *(const float4*)(w2 + j * 68 + j0 + 4);
                float ta[4] = {tv.x, tv.y, tv.z, tv.w};
                float wb[8] = {wA.x, wA.y, wA.z, wA.w, wB.x, wB.y, wB.z, wB.w};
                #pragma unroll
                for (int aa = 0; aa < 4; aa++)
                    #pragma unroll
                    for (int bb = 0; bb < 8; bb++)
                        acc2[aa][bb] = fmaf(ta[aa], wb[bb], acc2[aa][bb]);
            }
            float* hgd = hgv + gg * 2048;
            #pragma unroll
            for (int aa = 0; aa < 4; aa++) {
                *(float4*)(hgd + (a0 + aa) * 64 + j0) =
                    make_float4(acc2[aa][0], acc2[aa][1], acc2[aa][2], acc2[aa][3]);
                *(float4*)(hgd + (a0 + aa) * 64 + j0 + 4) =
                    make_float4(acc2[aa][4], acc2[aa][5], acc2[aa][6], acc2[aa][7]);
            }
        } else {
            asm volatile("cp.async.wait_group 0;");
        }
        __syncthreads();
        // peer done reading hs -> safe to overwrite both copies
        asm volatile("barrier.cluster.wait.aligned;" ::: "memory");

        // epilogue (all 256 threads): gates, c/h update, stores
        {
            int base = e_al * 64 + e_b0;
            float hv[8];
            #pragma unroll
            for (int k = 0; k < 8; k++) {
                float z = sigm(hgv[base + k]        + xgs[base + k]);
                float r = sigm(hgv[2048 + base + k] + xgs[2048 + base + k]);
                float o = sigm(hgv[4096 + base + k] + xgs[4096 + base + k]);
                c[k] = r * (c[k] + z);
                hv[k] = o * sigm(c[k]);
            }
            float* od = out + ((size_t)(n * LS + t)) * 4096 + (A0 + e_al) * 64 + e_b0;
            *(float4*)(od)     = make_float4(hv[0], hv[1], hv[2], hv[3]);
            *(float4*)(od + 4) = make_float4(hv[4], hv[5], hv[6], hv[7]);
            float* hl = hs + (A0 + e_al) * 64 + e_b0;
            *(float4*)(hl)     = make_float4(hv[0], hv[1], hv[2], hv[3]);
            *(float4*)(hl + 4) = make_float4(hv[4], hv[5], hv[6], hv[7]);
            uint32_t rp = hs_peer + (uint32_t)(((A0 + e_al) * 64 + e_b0) << 2);
            #pragma unroll
            for (int k = 0; k < 8; k += 2) {
                uint64_t pv;
                asm("mov.b64 %0, {%1,%2};" : "=l"(pv) : "f"(hv[k]), "f"(hv[k + 1]));
                asm volatile("st.shared::cluster.b64 [%0], %1;"
                             :: "r"(rp + (uint32_t)(k * 4)), "l"(pv));
            }
        }
        // full cluster sync: all h writes (local + remote) visible before next step
        asm volatile("barrier.cluster.arrive.aligned;" ::: "memory");
        asm volatile("barrier.cluster.wait.aligned;" ::: "memory");
    }

    // h_last (each CTA writes its own half)
    {
        float* hl = out + (size_t)NB * LS * 4096 + (size_t)n * 4096 + A0 * 64;
        const float* hsrc = hs + A0 * 64;
        #pragma unroll
        for (int k = 0; k < 8; k++) hl[tid + 256 * k] = hsrc[tid + 256 * k];
    }
    // c_last (from registers)
    {
        float* cl = out + (size_t)NB * LS * 4096 + (size_t)NB * 4096
                        + (size_t)n * 4096 + (A0 + e_al) * 64 + e_b0;
        *(float4*)(cl)     = make_float4(c[0], c[1], c[2], c[3]);
        *(float4*)(cl + 4) = make_float4(c[4], c[5], c[6], c[7]);
    }
}

// ---------------------------------------------------------------------------

extern "C" void kernel_launch(void* const* d_in, const int* in_sizes, int n_in,
                              void* d_out, int out_size)
{
    const float* x   = (const float*)d_in[0];
    const float* Ww1 = (const float*)d_in[1];
    const float* Ww2 = (const float*)d_in[2];
    const float* Wu1 = (const float*)d_in[3];
    const float* Wu2 = (const float*)d_in[4];
    float* out = (float*)d_out;

    float* xg = nullptr;
    cudaGetSymbolAddress((void**)&xg, g_xg);

    const size_t smem1 = (4096 + 9 * 64 * 68) * sizeof(float);                    // 173056
    const size_t smem2 = (4096 + 6912 + 13056 + 6912 + 6144 + 6144) * sizeof(float); // 173056

    cudaFuncSetAttribute(phase1_kernel, cudaFuncAttributeMaxDynamicSharedMemorySize, (int)smem1);
    cudaFuncSetAttribute(phase2_kernel, cudaFuncAttributeMaxDynamicSharedMemorySize, (int)smem2);

    phase1_kernel<<<NB * LS, 192, smem1>>>(x, Ww1, Ww2, xg);
    phase2_kernel<<<2 * NB, 256, smem2>>>(Wu1, Wu2, xg, out);
}

// round 3
// speedup vs baseline: 1.5636x; 1.0007x over previous
#include <cuda_runtime.h>
#include <cstdint>
#include <cstddef>

// LstmTl: N=64, L=128, D=H=64, 3 gates.
// Phase 1: xg[l,g,n,a,b] = sum_{i,j} x[n,l,i,j] * Ww1[g,a,i] * Ww2[g,b,j]
//          one CTA per (n,l), 192 threads = 3 gate-groups of 64, 8x8 reg tiles.
// Phase 2: cluster of 2 CTAs per n; each CTA owns 32 a-rows of all 3 gates.
//          h halves exchanged via DSMEM stores + cluster barriers.

#define NB 64
#define LS 128

__device__ float g_xg[(size_t)LS * 3 * NB * 4096];

__device__ __forceinline__ float sigm(float x) {
    return 1.0f / (1.0f + __expf(-x));
}

// ---------------------------------------------------------------------------
// Phase 1
// smem: xs[64][64] | W1t[3][64][68] (g,i,a) | W2t[3][64][68] (g,j,b) | ts[3][64][68] (g,j,a)
// ---------------------------------------------------------------------------
__global__ void __launch_bounds__(192, 1) phase1_kernel(
    const float* __restrict__ x,     // (N, L, 64, 64)
    const float* __restrict__ Ww1,   // (4, 64, 64) g,a,i
    const float* __restrict__ Ww2,   // (4, 64, 64) g,b,j
    float* __restrict__ xg)          // (L, 3, N, 64, 64)
{
    extern __shared__ float sm[];
    float* xs  = sm;                    // 4096
    float* W1t = sm + 4096;             // 3*64*68
    float* W2t = W1t + 3 * 64 * 68;     // 3*64*68
    float* ts  = W2t + 3 * 64 * 68;     // 3*64*68

    const int tid = threadIdx.x;
    const int n = blockIdx.x >> 7;
    const int l = blockIdx.x & 127;

    // load x[n,l] (16KB)
    {
        const float4* src = (const float4*)(x + ((size_t)(n * LS + l)) * 4096);
        #pragma unroll
        for (int k = 0; k < 6; k++) {
            int idx = tid + 192 * k;
            if (idx < 1024) ((float4*)xs)[idx] = src[idx];
        }
    }
    // load + transpose weights (3 gates each)
    #pragma unroll
    for (int k = 0; k < 16; k++) {
        int e4 = tid + 192 * k;                 // 0..3071
        float4 v1 = ((const float4*)Ww1)[e4];
        float4 v2 = ((const float4*)Ww2)[e4];
        int e = e4 * 4;
        int g = e >> 12, r = e & 4095;
        int row = r >> 6, col = r & 63;         // Ww1: row=a, col=i ; Ww2: row=b, col=j
        float* p1 = W1t + (g * 64 + col) * 68 + row;
        p1[0] = v1.x; p1[68] = v1.y; p1[136] = v1.z; p1[204] = v1.w;
        float* p2 = W2t + (g * 64 + col) * 68 + row;
        p2[0] = v2.x; p2[68] = v2.y; p2[136] = v2.z; p2[204] = v2.w;
    }
    __syncthreads();

    const int g  = tid >> 6;          // gate 0..2
    const int q  = tid & 63;
    const int a0 = (q >> 3) * 8;
    const int j0 = (q & 7) * 8;

    // stage1: tmp[a][j] = sum_i W1[a][i] * x[i][j]   (store transposed ts[j][a])
    float acc[8][8];
    #pragma unroll
    for (int aa = 0; aa < 8; aa++)
        #pragma unroll
        for (int jj = 0; jj < 8; jj++) acc[aa][jj] = 0.0f;

    const float* w1 = W1t + g * 64 * 68;
    #pragma unroll 4
    for (int i = 0; i < 64; i++) {
        float4 wA = *(const float4*)(w1 + i * 68 + a0);
        float4 wB = *(const float4*)(w1 + i * 68 + a0 + 4);
        float4 xA = *(const float4*)(xs + i * 64 + j0);
        float4 xB = *(const float4*)(xs + i * 64 + j0 + 4);
        float wa[8] = {wA.x, wA.y, wA.z, wA.w, wB.x, wB.y, wB.z, wB.w};
        float xv[8] = {xA.x, xA.y, xA.z, xA.w, xB.x, xB.y, xB.z, xB.w};
        #pragma unroll
        for (int aa = 0; aa < 8; aa++)
            #pragma unroll
            for (int jj = 0; jj < 8; jj++)
                acc[aa][jj] = fmaf(wa[aa], xv[jj], acc[aa][jj]);
    }
    float* tsg = ts + g * 64 * 68;
    #pragma unroll
    for (int jj = 0; jj < 8; jj++) {
        *(float4*)(tsg + (j0 + jj) * 68 + a0) =
            make_float4(acc[0][jj], acc[1][jj], acc[2][jj], acc[3][jj]);
        *(float4*)(tsg + (j0 + jj) * 68 + a0 + 4) =
            make_float4(acc[4][jj], acc[5][jj], acc[6][jj], acc[7][jj]);
    }
    __syncthreads();

    // stage2: xg[a][b] = sum_j ts[j][a] * W2[b][j]
    const int b0 = j0;
    float acc2[8][8];
    #pragma unroll
    for (int aa = 0; aa < 8; aa++)
        #pragma unroll
        for (int bb = 0; bb < 8; bb++) acc2[aa][bb] = 0.0f;

    const float* w2 = W2t + g * 64 * 68;
    #pragma unroll 4
    for (int j = 0; j < 64; j++) {
        float4 tA = *(const float4*)(tsg + j * 68 + a0);
        float4 tB = *(const float4*)(tsg + j * 68 + a0 + 4);
        float4 wA = *(const float4*)(w2 + j * 68 + b0);
        float4 wB = *(const float4*)(w2 + j * 68 + b0 + 4);
        float ta[8] = {tA.x, tA.y, tA.z, tA.w, tB.x, tB.y, tB.z, tB.w};
        float wb[8] = {wA.x, wA.y, wA.z, wA.w, wB.x, wB.y, wB.z, wB.w};
        #pragma unroll
        for (int aa = 0; aa < 8; aa++)
            #pragma unroll
            for (int bb = 0; bb < 8; bb++)
                acc2[aa][bb] = fmaf(ta[aa], wb[bb], acc2[aa][bb]);
    }
    float* dst = xg + ((size_t)((l * 3 + g) * NB + n)) * 4096;
    #pragma unroll
    for (int aa = 0; aa < 8; aa++) {
        *(float4*)(dst + (a0 + aa) * 64 + b0) =
            make_float4(acc2[aa][0], acc2[aa][1], acc2[aa][2], acc2[aa][3]);
        *(float4*)(dst + (a0 + aa) * 64 + b0 + 4) =
            make_float4(acc2[aa][4], acc2[aa][5], acc2[aa][6], acc2[aa][7]);
    }
}

// ---------------------------------------------------------------------------
// Phase 2: grid 128 = 2 per n, cluster (2,1,1), 256 threads.
// CTA rank r owns a-rows [32r, 32r+32) of all gates; full h replicated in both.
// smem: hs[64][64] | W1t[3][64][36] | W2t[3][64][68] | ts[3][64][36] |
//       hg[3][32][64] | xgs[3][32][64]
// ---------------------------------------------------------------------------
__global__ void __launch_bounds__(256, 1) __cluster_dims__(2, 1, 1) phase2_kernel(
    const float* __restrict__ Wu1,   // (4,64,64) g,a,i
    const float* __restrict__ Wu2,   // (4,64,64) g,b,j
    const float* __restrict__ xg,    // (L,3,N,64,64)
    float* __restrict__ out)         // outs | h_last | c_last
{
    extern __shared__ float sm[];
    float* hs  = sm;                 // 4096
    float* W1t = sm + 4096;          // 3*64*36 = 6912  [g][i][a_loc]
    float* W2t = W1t + 6912;         // 3*64*68 = 13056 [g][j][b]
    float* ts  = W2t + 13056;        // 3*64*36 = 6912  [g][j][a_loc]
    float* hgv = ts + 6912;          // 3*32*64 = 6144
    float* xgs = hgv + 6144;         // 6144

    const int tid = threadIdx.x;
    uint32_t rk;
    asm("mov.u32 %0, %%cluster_ctarank;" : "=r"(rk));
    const int n  = blockIdx.x >> 1;
    const int A0 = (int)rk * 32;

    // W1t[g][i][al] = Wu1[g][A0+al][i]
    #pragma unroll
    for (int k = 0; k < 24; k++) {
        int idx = tid + 256 * k;                 // < 6144
        int g = idx / 2048, rem = idx & 2047;
        int al = rem >> 6, i = rem & 63;
        W1t[(g * 64 + i) * 36 + al] = Wu1[g * 4096 + (A0 + al) * 64 + i];
    }
    // W2t[g][j][b] = Wu2[g][b][j]
    #pragma unroll
    for (int k = 0; k < 48; k++) {
        int idx = tid + 256 * k;                 // < 12288
        int g = idx >> 12, rem = idx & 4095;
        int b = rem >> 6, j = rem & 63;
        W2t[(g * 64 + j) * 68 + b] = Wu2[idx];
    }
    #pragma unroll
    for (int k = 0; k < 16; k++) hs[tid + 256 * k] = 0.0f;

    uint32_t hs_local = (uint32_t)__cvta_generic_to_shared(hs);
    uint32_t hs_peer;
    asm("mapa.shared::cluster.u32 %0, %1, %2;"
        : "=r"(hs_peer) : "r"(hs_local), "r"(rk ^ 1u));

    const int gg = tid >> 6;          // 0..2 matmul groups, 3 = cp.async group
    const int q  = tid & 63;
    const int a0 = (q >> 3) * 4;      // a_loc tile base (stage1/2)
    const int j0 = (q & 7) * 8;       // j / b tile base
    const int e_al = tid >> 3;        // epilogue row 0..31
    const int e_b0 = (tid & 7) * 8;

    float c[8];
    #pragma unroll
    for (int k = 0; k < 8; k++) c[k] = 0.0f;

    __syncthreads();
    asm volatile("barrier.cluster.arrive.aligned;" ::: "memory");
    asm volatile("barrier.cluster.wait.aligned;" ::: "memory");

    for (int t = 0; t < LS; t++) {
        if (gg == 3) {
            // prefetch xg slab for this step: 3 gates x 32 rows x 256B
            #pragma unroll
            for (int k = 0; k < 24; k++) {
                int cc = q + 64 * k;                      // < 1536 16B-chunks
                int gx = cc >> 9, rem = cc & 511;
                int row = rem >> 4, off = rem & 15;
                const float* src = xg + ((size_t)((t * 3 + gx) * NB + n)) * 4096
                                      + (A0 + row) * 64 + off * 4;
                uint32_t dsts = (uint32_t)__cvta_generic_to_shared(
                    xgs + gx * 2048 + row * 64 + off * 4);
                asm volatile("cp.async.ca.shared.global [%0], [%1], 16;"
                             :: "r"(dsts), "l"(src));
            }
            asm volatile("cp.async.commit_group;");
        } else {
            // stage1: ts[g][j][al] = sum_i W1t[g][i][al] * hs[i][j]
            float acc[4][8];
            #pragma unroll
            for (int aa = 0; aa < 4; aa++)
                #pragma unroll
                for (int jj = 0; jj < 8; jj++) acc[aa][jj] = 0.0f;
            const float* w1 = W1t + gg * 64 * 36;
            #pragma unroll 4
            for (int i = 0; i < 64; i++) {
                float4 wv = *(const float4*)(w1 + i * 36 + a0);
                float4 hA = *(const float4*)(hs + i * 64 + j0);
                float4 hB = *(const float4*)(hs + i * 64 + j0 + 4);
                float wa[4] = {wv.x, wv.y, wv.z, wv.w};
                float hv[8] = {hA.x, hA.y, hA.z, hA.w, hB.x, hB.y, hB.z, hB.w};
                #pragma unroll
                for (int aa = 0; aa < 4; aa++)
                    #pragma unroll
                    for (int jj = 0; jj < 8; jj++)
                        acc[aa][jj] = fmaf(wa[aa], hv[jj], acc[aa][jj]);
            }
            float* tg = ts + gg * 64 * 36;
            #pragma unroll
            for (int jj = 0; jj < 8; jj++)
                *(float4*)(tg + (j0 + jj) * 36 + a0) =
                    make_float4(acc[0][jj], acc[1][jj], acc[2][jj], acc[3][jj]);
        }
        __syncthreads();
        // my CTA is done reading hs for this step
        asm volatile("barrier.cluster.arrive.aligned;" ::: "memory");

        if (gg < 3) {
            // stage2: hg[al][b] = sum_j ts[g][j][al] * W2t[g][j][b]
            float acc2[4][8];
            #pragma unroll
            for (int aa = 0; aa < 4; aa++)
                #pragma unroll
                for (int bb = 0; bb < 8; bb++) acc2[aa][bb] = 0.0f;
            const float* w2 = W2t + gg * 64 * 68;
            const float* tg = ts + gg * 64 * 36;
            #pragma unroll 4
            for (int j = 0; j < 64; j++) {
                float4 tv = *(const float4*)(tg + j * 36 + a0);
                float4 wA = *(const float4*)(w2 + j * 68 + j0);
                float4 wB = *(const float4*)(w2 + j * 68 + j0 + 4);
                float ta[4] = {tv.x, tv.y, tv.z, tv.w};
                float wb[8] = {wA.x, wA.y, wA.z, wA.w, wB.x, wB.y, wB.z, wB.w};
                #pragma unroll
                for (int aa = 0; aa < 4; aa++)
                    #pragma unroll
                    for (int bb = 0; bb < 8; bb++)
                        acc2[aa][bb] = fmaf(ta[aa], wb[bb], acc2[aa][bb]);
            }
            float* hgd = hgv + gg * 2048;
            #pragma unroll
            for (int aa = 0; aa < 4; aa++) {
                *(float4*)(hgd + (a0 + aa) * 64 + j0) =
                    make_float4(acc2[aa][0], acc2[aa][1], acc2[aa][2], acc2[aa][3]);
                *(float4*)(hgd + (a0 + aa) * 64 + j0 + 4) =
                    make_float4(acc2[aa][4], acc2[aa][5], acc2[aa][6], acc2[aa][7]);
            }
        } else {
            asm volatile("cp.async.wait_group 0;");
        }
        __syncthreads();
        // peer done reading hs -> safe to overwrite both copies
        asm volatile("barrier.cluster.wait.aligned;" ::: "memory");

        // epilogue (all 256 threads): gates, c/h update, stores
        {
            int base = e_al * 64 + e_b0;
            float hv[8];
            #pragma unroll
            for (int k = 0; k < 8; k++) {
                float z = sigm(hgv[base + k]        + xgs[base + k]);
                float r = sigm(hgv[2048 + base + k] + xgs[2048 + base + k]);
                float o = sigm(hgv[4096 + base + k] + xgs[4096 + base + k]);
                c[k] = r * (c[k] + z);
                hv[k] = o * sigm(c[k]);
            }
            float* od = out + ((size_t)(n * LS + t)) * 4096 + (A0 + e_al) * 64 + e_b0;
            *(float4*)(od)     = make_float4(hv[0], hv[1], hv[2], hv[3]);
            *(float4*)(od + 4) = make_float4(hv[4], hv[5], hv[6], hv[7]);
            float* hl = hs + (A0 + e_al) * 64 + e_b0;
            *(float4*)(hl)     = make_float4(hv[0], hv[1], hv[2], hv[3]);
            *(float4*)(hl + 4) = make_float4(hv[4], hv[5], hv[6], hv[7]);
            uint32_t rp = hs_peer + (uint32_t)(((A0 + e_al) * 64 + e_b0) << 2);
            #pragma unroll
            for (int k = 0; k < 8; k += 2) {
                uint64_t pv;
                asm("mov.b64 %0, {%1,%2};" : "=l"(pv) : "f"(hv[k]), "f"(hv[k + 1]));
                asm volatile("st.shared::cluster.b64 [%0], %1;"
                             :: "r"(rp + (uint32_t)(k * 4)), "l"(pv));
            }
        }
        // full cluster sync: all h writes (local + remote) visible before next step
        asm volatile("barrier.cluster.arrive.aligned;" ::: "memory");
        asm volatile("barrier.cluster.wait.aligned;" ::: "memory");
    }

    // h_last (each CTA writes its own half)
    {
        float* hl = out + (size_t)NB * LS * 4096 + (size_t)n * 4096 + A0 * 64;
        const float* hsrc = hs + A0 * 64;
        #pragma unroll
        for (int k = 0; k < 8; k++) hl[tid + 256 * k] = hsrc[tid + 256 * k];
    }
    // c_last (from registers)
    {
        float* cl = out + (size_t)NB * LS * 4096 + (size_t)NB * 4096
                        + (size_t)n * 4096 + (A0 + e_al) * 64 + e_b0;
        *(float4*)(cl)     = make_float4(c[0], c[1], c[2], c[3]);
        *(float4*)(cl + 4) = make_float4(c[4], c[5], c[6], c[7]);
    }
}

// ---------------------------------------------------------------------------

extern "C" void kernel_launch(void* const* d_in, const int* in_sizes, int n_in,
                              void* d_out, int out_size)
{
    const float* x   = (const float*)d_in[0];
    const float* Ww1 = (const float*)d_in[1];
    const float* Ww2 = (const float*)d_in[2];
    const float* Wu1 = (const float*)d_in[3];
    const float* Wu2 = (const float*)d_in[4];
    float* out = (float*)d_out;

    float* xg = nullptr;
    cudaGetSymbolAddress((void**)&xg, g_xg);

    const size_t smem1 = (4096 + 9 * 64 * 68) * sizeof(float);                    // 173056
    const size_t smem2 = (4096 + 6912 + 13056 + 6912 + 6144 + 6144) * sizeof(float); // 173056

    cudaFuncSetAttribute(phase1_kernel, cudaFuncAttributeMaxDynamicSharedMemorySize, (int)smem1);
    cudaFuncSetAttribute(phase2_kernel, cudaFuncAttributeMaxDynamicSharedMemorySize, (int)smem2);

    phase1_kernel<<<NB * LS, 192, smem1>>>(x, Ww1, Ww2, xg);
    phase2_kernel<<<2 * NB, 256, smem2>>>(Wu1, Wu2, xg, out);
}

// round 4
// speedup vs baseline: 1.8180x; 1.1627x over previous
#include <cuda_runtime.h>
#include <cstdint>
#include <cstddef>

#define NB 64
#define LS 128

__device__ float g_xg[(size_t)LS * 3 * NB * 4096];

__device__ __forceinline__ float sigm(float x){ return 1.0f/(1.0f+__expf(-x)); }

__device__ __forceinline__ uint64_t pk2(float x, float y){
    uint64_t r; asm("mov.b64 %0, {%1, %2};" : "=l"(r) : "f"(x), "f"(y)); return r;
}
__device__ __forceinline__ void upk2(uint64_t v, float& x, float& y){
    asm("mov.b64 {%0, %1}, %2;" : "=f"(x), "=f"(y) : "l"(v));
}
__device__ __forceinline__ void fma2(uint64_t& d, uint64_t a, uint64_t b){
    asm("fma.rn.f32x2 %0, %1, %2, %0;" : "+l"(d) : "l"(a), "l"(b));
}
__device__ __forceinline__ void cpa16(void* dst, const float* src){
    asm volatile("cp.async.ca.shared.global [%0], [%1], 16;"
                 :: "r"((uint32_t)__cvta_generic_to_shared(dst)), "l"(src));
}

// ---------------------------------------------------------------------------
// Phase 1: persistent, 384 threads (3 gate groups x 128), f32x2, x double-buf.
// smem: xs[2][4096] | W1t[3][64][68] (i,a) | W2t[3][64][68] (j,b) | ts[3][64][68] (j,a)
// ---------------------------------------------------------------------------
__global__ void __launch_bounds__(384,1) phase1_kernel(
    const float* __restrict__ x, const float* __restrict__ Ww1,
    const float* __restrict__ Ww2, float* __restrict__ xg)
{
    extern __shared__ float sm[];
    float* xs  = sm;            // 8192
    float* W1t = sm + 8192;     // 13056
    float* W2t = W1t + 13056;   // 13056
    float* ts  = W2t + 13056;   // 13056
    const int tid = threadIdx.x;

    for (int idx = tid; idx < 12288; idx += 384) {
        int g = idx >> 12, r = idx & 4095, row = r >> 6, col = r & 63;
        W1t[(g*64+col)*68+row] = Ww1[idx];   // [g][i][a]
        W2t[(g*64+col)*68+row] = Ww2[idx];   // [g][j][b]
    }

    const int gg = tid / 128, q = tid % 128;
    const int a0 = (q >> 3) * 4, j0 = (q & 7) * 8;

    int p = blockIdx.x;
    {
        const float* src = x + (size_t)p * 4096;
        #pragma unroll
        for (int k = 0; k < 3; k++) {
            int idx = tid + 384*k;
            if (idx < 1024) cpa16(xs + idx*4, src + idx*4);
        }
        asm volatile("cp.async.commit_group;");
        asm volatile("cp.async.wait_group 0;");
    }
    __syncthreads();

    int buf = 0;
    for (; p < NB*LS; p += gridDim.x) {
        int pn = p + gridDim.x;
        if (pn < NB*LS) {
            const float* src = x + (size_t)pn * 4096;
            float* xd = xs + (buf^1)*4096;
            #pragma unroll
            for (int k = 0; k < 3; k++) {
                int idx = tid + 384*k;
                if (idx < 1024) cpa16(xd + idx*4, src + idx*4);
            }
            asm volatile("cp.async.commit_group;");
        }
        const float* xb = xs + buf*4096;
        const float* w1 = W1t + gg*4352;
        float* tg = ts + gg*4352;

        // stage1: tmp[a][j] = sum_i W1[a][i]*x[i][j]
        uint64_t acc[4][4];
        #pragma unroll
        for (int aa=0; aa<4; aa++)
            #pragma unroll
            for (int pp=0; pp<4; pp++) acc[aa][pp] = 0;
        #pragma unroll 4
        for (int i = 0; i < 64; i++) {
            float4 wv = *(const float4*)(w1 + i*68 + a0);
            ulonglong2 hA = *(const ulonglong2*)(xb + i*64 + j0);
            ulonglong2 hB = *(const ulonglong2*)(xb + i*64 + j0 + 4);
            uint64_t hp[4] = {hA.x, hA.y, hB.x, hB.y};
            uint64_t wp[4] = {pk2(wv.x,wv.x), pk2(wv.y,wv.y), pk2(wv.z,wv.z), pk2(wv.w,wv.w)};
            #pragma unroll
            for (int aa=0; aa<4; aa++)
                #pragma unroll
                for (int pp=0; pp<4; pp++) fma2(acc[aa][pp], wp[aa], hp[pp]);
        }
        {   // write ts[j][a]
            float f[4][8];
            #pragma unroll
            for (int aa=0; aa<4; aa++)
                #pragma unroll
                for (int pp=0; pp<4; pp++) upk2(acc[aa][pp], f[aa][2*pp], f[aa][2*pp+1]);
            #pragma unroll
            for (int jj=0; jj<8; jj++)
                *(float4*)(tg + (j0+jj)*68 + a0) =
                    make_float4(f[0][jj], f[1][jj], f[2][jj], f[3][jj]);
        }
        __syncthreads();

        // stage2: out[a][b] = sum_j tmp[a][j]*W2[b][j]
        const float* w2 = W2t + gg*4352;
        const int b0 = j0;
        uint64_t ac2[4][4];
        #pragma unroll
        for (int aa=0; aa<4; aa++)
            #pragma unroll
            for (int pp=0; pp<4; pp++) ac2[aa][pp] = 0;
        #pragma unroll 4
        for (int j = 0; j < 64; j++) {
            float4 tv = *(const float4*)(tg + j*68 + a0);
            ulonglong2 wA = *(const ulonglong2*)(w2 + j*68 + b0);
            ulonglong2 wB = *(const ulonglong2*)(w2 + j*68 + b0 + 4);
            uint64_t wpr[4] = {wA.x, wA.y, wB.x, wB.y};
            uint64_t tp[4] = {pk2(tv.x,tv.x), pk2(tv.y,tv.y), pk2(tv.z,tv.z), pk2(tv.w,tv.w)};
            #pragma unroll
            for (int aa=0; aa<4; aa++)
                #pragma unroll
                for (int pp=0; pp<4; pp++) fma2(ac2[aa][pp], tp[aa], wpr[pp]);
        }
        {
            int n = p >> 7, l = p & 127;
            float* dst = xg + ((size_t)((l*3+gg)*NB + n))*4096;
            #pragma unroll
            for (int aa=0; aa<4; aa++) {
                float g0,g1,g2,g3,g4,g5,g6,g7;
                upk2(ac2[aa][0],g0,g1); upk2(ac2[aa][1],g2,g3);
                upk2(ac2[aa][2],g4,g5); upk2(ac2[aa][3],g6,g7);
                *(float4*)(dst + (a0+aa)*64 + b0)     = make_float4(g0,g1,g2,g3);
                *(float4*)(dst + (a0+aa)*64 + b0 + 4) = make_float4(g4,g5,g6,g7);
            }
        }
        asm volatile("cp.async.wait_group 0;");
        __syncthreads();
        buf ^= 1;
    }
}

// ---------------------------------------------------------------------------
// Phase 2: cluster(2) per n, 384 threads, all warps compute, f32x2.
// ---------------------------------------------------------------------------
__global__ void __launch_bounds__(384,1) __cluster_dims__(2,1,1) phase2_kernel(
    const float* __restrict__ Wu1, const float* __restrict__ Wu2,
    const float* __restrict__ xg, float* __restrict__ out)
{
    extern __shared__ float sm[];
    float* hs  = sm;           // 4096
    float* W1t = sm + 4096;    // 6912  [g][i][36->al]
    float* W2t = W1t + 6912;   // 13056 [g][j][68->b]
    float* ts  = W2t + 13056;  // 6912  [g][j][36->al]
    float* hgv = ts + 6912;    // 6144
    float* xgs = hgv + 6144;   // 6144

    const int tid = threadIdx.x;
    uint32_t rk; asm("mov.u32 %0, %%cluster_ctarank;" : "=r"(rk));
    const int n = blockIdx.x >> 1;
    const int A0 = (int)rk * 32;

    for (int idx = tid; idx < 6144; idx += 384) {
        int g = idx / 2048, r = idx & 2047, al = r >> 6, i = r & 63;
        W1t[(g*64+i)*36+al] = Wu1[g*4096 + (A0+al)*64 + i];
    }
    for (int idx = tid; idx < 12288; idx += 384) {
        int g = idx >> 12, r = idx & 4095, b = r >> 6, j = r & 63;
        W2t[(g*64+j)*68+b] = Wu2[idx];
    }
    for (int idx = tid; idx < 4096; idx += 384) hs[idx] = 0.0f;

    uint32_t hs_peer;
    { uint32_t hl = (uint32_t)__cvta_generic_to_shared(hs);
      asm("mapa.shared::cluster.u32 %0, %1, %2;" : "=r"(hs_peer) : "r"(hl), "r"(rk^1u)); }

    const int gg = tid / 128, q = tid % 128;
    const int al0 = (q >> 4) * 4, j0 = (q & 15) * 4;
    const int e_al = (tid >> 3) & 31, e_b0 = (tid & 7) * 8;

    float c[8];
    #pragma unroll
    for (int k=0;k<8;k++) c[k]=0.0f;

    __syncthreads();
    asm volatile("barrier.cluster.arrive.aligned;" ::: "memory");
    asm volatile("barrier.cluster.wait.aligned;" ::: "memory");

    for (int t = 0; t < LS; t++) {
        // prefetch xg slab (all threads, 4 chunks each)
        #pragma unroll
        for (int k = 0; k < 4; k++) {
            int cc = tid + 384*k;
            int gx = cc >> 9, r = cc & 511, row = r >> 4, off = r & 15;
            const float* src = xg + ((size_t)((t*3+gx)*NB + n))*4096 + (A0+row)*64 + off*4;
            cpa16(xgs + gx*2048 + row*64 + off*4, src);
        }
        asm volatile("cp.async.commit_group;");

        // stage1: ts[g][j][al] = sum_i W1t[g][i][al] * hs[i][j]
        const float* w1 = W1t + gg*2304;
        float* tg = ts + gg*2304;
        uint64_t acc[4][2];
        #pragma unroll
        for (int aa=0; aa<4; aa++) { acc[aa][0]=0; acc[aa][1]=0; }
        #pragma unroll 4
        for (int i = 0; i < 64; i++) {
            float4 wv = *(const float4*)(w1 + i*36 + al0);
            ulonglong2 hv = *(const ulonglong2*)(hs + i*64 + j0);
            uint64_t wp[4] = {pk2(wv.x,wv.x), pk2(wv.y,wv.y), pk2(wv.z,wv.z), pk2(wv.w,wv.w)};
            #pragma unroll
            for (int aa=0; aa<4; aa++) {
                fma2(acc[aa][0], wp[aa], hv.x);
                fma2(acc[aa][1], wp[aa], hv.y);
            }
        }
        {
            float f[4][4];
            #pragma unroll
            for (int aa=0; aa<4; aa++) {
                upk2(acc[aa][0], f[aa][0], f[aa][1]);
                upk2(acc[aa][1], f[aa][2], f[aa][3]);
            }
            #pragma unroll
            for (int jj=0; jj<4; jj++)
                *(float4*)(tg + (j0+jj)*36 + al0) =
                    make_float4(f[0][jj], f[1][jj], f[2][jj], f[3][jj]);
        }
        __syncthreads();
        asm volatile("barrier.cluster.arrive.aligned;" ::: "memory");

        // stage2: hg[al][b] = sum_j ts[g][j][al] * W2t[g][j][b]
        const float* w2 = W2t + gg*4352;
        uint64_t ac2[4][2];
        #pragma unroll
        for (int aa=0; aa<4; aa++) { ac2[aa][0]=0; ac2[aa][1]=0; }
        #pragma unroll 4
        for (int j = 0; j < 64; j++) {
            float4 tv = *(const float4*)(tg + j*36 + al0);
            ulonglong2 wv = *(const ulonglong2*)(w2 + j*68 + j0);
            uint64_t tp[4] = {pk2(tv.x,tv.x), pk2(tv.y,tv.y), pk2(tv.z,tv.z), pk2(tv.w,tv.w)};
            #pragma unroll
            for (int aa=0; aa<4; aa++) {
                fma2(ac2[aa][0], tp[aa], wv.x);
                fma2(ac2[aa][1], tp[aa], wv.y);
            }
        }
        {
            float* hgd = hgv + gg*2048;
            #pragma unroll
            for (int aa=0; aa<4; aa++) {
                ulonglong2 v; v.x = ac2[aa][0]; v.y = ac2[aa][1];
                *(ulonglong2*)(hgd + (al0+aa)*64 + j0) = v;
            }
        }
        asm volatile("cp.async.wait_group 0;");
        __syncthreads();
        asm volatile("barrier.cluster.wait.aligned;" ::: "memory");

        if (tid < 256) {
            int base = e_al*64 + e_b0;
            float hv[8];
            #pragma unroll
            for (int k=0;k<8;k++) {
                float z = sigm(hgv[base+k]        + xgs[base+k]);
                float r = sigm(hgv[2048+base+k]   + xgs[2048+base+k]);
                float o = sigm(hgv[4096+base+k]   + xgs[4096+base+k]);
                c[k] = r * (c[k] + z);
                hv[k] = o * sigm(c[k]);
            }
            float* od = out + ((size_t)(n*LS+t))*4096 + (A0+e_al)*64 + e_b0;
            *(float4*)(od)     = make_float4(hv[0],hv[1],hv[2],hv[3]);
            *(float4*)(od + 4) = make_float4(hv[4],hv[5],hv[6],hv[7]);
            float* hl = hs + (A0+e_al)*64 + e_b0;
            *(float4*)(hl)     = make_float4(hv[0],hv[1],hv[2],hv[3]);
            *(float4*)(hl + 4) = make_float4(hv[4],hv[5],hv[6],hv[7]);
            uint32_t rp = hs_peer + (uint32_t)(((A0+e_al)*64 + e_b0) << 2);
            #pragma unroll
            for (int k=0; k<8; k+=2) {
                uint64_t pv = pk2(hv[k], hv[k+1]);
                asm volatile("st.shared::cluster.b64 [%0], %1;"
                             :: "r"(rp + (uint32_t)(k*4)), "l"(pv));
            }
        }
        asm volatile("barrier.cluster.arrive.aligned;" ::: "memory");
        asm volatile("barrier.cluster.wait.aligned;" ::: "memory");
    }

    for (int idx = tid; idx < 2048; idx += 384)
        out[(size_t)NB*LS*4096 + (size_t)n*4096 + A0*64 + idx] = hs[A0*64 + idx];
    if (tid < 256) {
        float* cl = out + (size_t)NB*LS*4096 + (size_t)NB*4096
                        + (size_t)n*4096 + (A0+e_al)*64 + e_b0;
        *(float4*)(cl)     = make_float4(c[0],c[1],c[2],c[3]);
        *(float4*)(cl + 4) = make_float4(c[4],c[5],c[6],c[7]);
    }
}

// ---------------------------------------------------------------------------

extern "C" void kernel_launch(void* const* d_in, const int* in_sizes, int n_in,
                              void* d_out, int out_size)
{
    const float* x   = (const float*)d_in[0];
    const float* Ww1 = (const float*)d_in[1];
    const float* Ww2 = (const float*)d_in[2];
    const float* Wu1 = (const float*)d_in[3];
    const float* Wu2 = (const float*)d_in[4];
    float* out = (float*)d_out;

    float* xg = nullptr;
    cudaGetSymbolAddress((void**)&xg, g_xg);

    const size_t smem1 = (8192 + 3 * 13056) * sizeof(float);   // 189440
    const size_t smem2 = (4096 + 6912 + 13056 + 6912 + 6144 + 6144) * sizeof(float); // 173056

    cudaFuncSetAttribute(phase1_kernel, cudaFuncAttributeMaxDynamicSharedMemorySize, (int)smem1);
    cudaFuncSetAttribute(phase2_kernel, cudaFuncAttributeMaxDynamicSharedMemorySize, (int)smem2);

    phase1_kernel<<<148, 384, smem1>>>(x, Ww1, Ww2, xg);
    phase2_kernel<<<2 * NB, 384, smem2>>>(Wu1, Wu2, xg, out);
}

// round 6
// speedup vs baseline: 2.7156x; 1.4937x over previous
#include <cuda_runtime.h>
#include <cuda_bf16.h>
#include <cstdint>
#include <cstddef>

#define NB 64
#define LS 128

__device__ float g_xg[(size_t)LS*3*NB*4096];

__device__ __forceinline__ float sigm(float x){ return 1.0f/(1.0f+__expf(-x)); }
__device__ __forceinline__ uint64_t pk2(float x, float y){
    uint64_t r; asm("mov.b64 %0, {%1, %2};" : "=l"(r) : "f"(x), "f"(y)); return r; }
__device__ __forceinline__ void upk2(uint64_t v, float& x, float& y){
    asm("mov.b64 {%0, %1}, %2;" : "=f"(x), "=f"(y) : "l"(v)); }
__device__ __forceinline__ void fma2(uint64_t& d, uint64_t a, uint64_t b){
    asm("fma.rn.f32x2 %0, %1, %2, %0;" : "+l"(d) : "l"(a), "l"(b)); }
__device__ __forceinline__ void cpa16(void* dst, const float* src){
    asm volatile("cp.async.ca.shared.global [%0], [%1], 16;"
                 :: "r"((uint32_t)__cvta_generic_to_shared(dst)), "l"(src)); }
__device__ __forceinline__ uint32_t smem_u32(const void* p){
    uint32_t a; asm("{ .reg .u64 t; cvta.to.shared.u64 t, %1; cvt.u32.u64 %0, t; }"
                    : "=r"(a) : "l"(p)); return a; }

// ---- bf16 split helpers ----
// split pair (f0,f1) -> hi bf16x2 (lo half = f0), lo-residual bf16x2
__device__ __forceinline__ uint2 split2(float f0, float f1){
    __nv_bfloat162 h2 = __floats2bfloat162_rn(f0, f1);
    uint32_t u = *(uint32_t*)&h2;
    float b0 = __uint_as_float(u << 16);
    float b1 = __uint_as_float(u & 0xffff0000u);
    __nv_bfloat162 l2 = __floats2bfloat162_rn(f0 - b0, f1 - b1);
    uint2 r; r.x = u; r.y = *(uint32_t*)&l2;
    return r;
}

// ---- mma.sync + ldmatrix (sm_80 path, valid under compute_103) ----
__device__ __forceinline__ void ldm4(uint32_t* r, uint32_t addr){
    asm volatile("ldmatrix.sync.aligned.m8n8.x4.shared.b16 {%0,%1,%2,%3}, [%4];"
        : "=r"(r[0]),"=r"(r[1]),"=r"(r[2]),"=r"(r[3]) : "r"(addr));
}
__device__ __forceinline__ void ldm4t(uint32_t* r, uint32_t addr){
    asm volatile("ldmatrix.sync.aligned.m8n8.x4.trans.shared.b16 {%0,%1,%2,%3}, [%4];"
        : "=r"(r[0]),"=r"(r[1]),"=r"(r[2]),"=r"(r[3]) : "r"(addr));
}
__device__ __forceinline__ void mma16816(float* d, const uint32_t* a, uint32_t b0, uint32_t b1){
    asm volatile("mma.sync.aligned.m16n8k16.row.col.f32.bf16.bf16.f32 "
        "{%0,%1,%2,%3}, {%4,%5,%6,%7}, {%8,%9}, {%0,%1,%2,%3};"
        : "+f"(d[0]),"+f"(d[1]),"+f"(d[2]),"+f"(d[3])
        : "r"(a[0]),"r"(a[1]),"r"(a[2]),"r"(a[3]), "r"(b0),"r"(b1));
}
// lane address into a 16x16 block of a row-major bf16 array with row stride 72
__device__ __forceinline__ uint32_t fraddr(uint32_t base, int row0, int col0, int lane){
    int grp = lane >> 3, lr = lane & 7;
    int row = row0 + lr + (grp & 1) * 8;
    int col = col0 + (grp >> 1) * 8;
    return base + (uint32_t)(row * 72 + col) * 2u;
}

// smem byte offsets (phase1), bf16 arrays with row stride 72 elems (144B)
#define P1_XH   0u
#define P1_XL   9216u
#define P1_W1H  18432u
#define P1_W1L  46080u
#define P1_W2H  73728u
#define P1_W2L  101376u
#define P1_BYTES 129024u

// ---------------------------------------------------------------------------
// Phase 1 (mma.sync bf16, 3-term split): persistent 148 CTAs, 384 thr = 12 warps.
// warp w -> gate g = w/4, rowblock rb = w%4 (a-rows 16rb..16rb+15).
// stage1: T = W1[g] @ X ; stage2: out = T @ W2t[g]; T stays in registers.
// ---------------------------------------------------------------------------
__global__ void __launch_bounds__(384,1) phase1_mma(
    const float* __restrict__ x, const float* __restrict__ Ww1,
    const float* __restrict__ Ww2, float* __restrict__ xg)
{
    extern __shared__ char sb[];
    const uint32_t s0 = smem_u32(sb);
    const int tid = threadIdx.x, wid = tid >> 5, lane = tid & 31;

    // ---- one-time weight prep: split bf16, W2 transposed ----
    if (tid < 192){
        const int g = tid >> 6, row = tid & 63;
        float w[64];
        #pragma unroll
        for (int q = 0; q < 16; q++)
            ((float4*)w)[q] = ((const float4*)(Ww1 + tid * 64))[q];
        uint32_t eb = (uint32_t)(g * 4608 + row * 72);
        #pragma unroll
        for (int k = 0; k < 32; k++){
            uint2 hl = split2(w[2*k], w[2*k+1]);
            *(uint32_t*)(sb + P1_W1H + (eb + 2*k)*2) = hl.x;
            *(uint32_t*)(sb + P1_W1L + (eb + 2*k)*2) = hl.y;
        }
        // W2t[g][j][b] = Ww2[g][b][j]
        #pragma unroll 4
        for (int b = 0; b < 64; b++) w[b] = Ww2[g * 4096 + b * 64 + row];
        #pragma unroll
        for (int k = 0; k < 32; k++){
            uint2 hl = split2(w[2*k], w[2*k+1]);
            *(uint32_t*)(sb + P1_W2H + (eb + 2*k)*2) = hl.x;
            *(uint32_t*)(sb + P1_W2L + (eb + 2*k)*2) = hl.y;
        }
    }

    const int g  = wid >> 2;      // 0..2
    const int rb = wid & 3;       // 0..3
    const uint32_t w1hB = s0 + P1_W1H + (uint32_t)g * 9216u;
    const uint32_t w1lB = s0 + P1_W1L + (uint32_t)g * 9216u;
    const uint32_t w2hB = s0 + P1_W2H + (uint32_t)g * 9216u;
    const uint32_t w2lB = s0 + P1_W2L + (uint32_t)g * 9216u;

    float4 xr[4];
    const int xi = tid >> 2, xj = (tid & 3) * 16;

    int p = blockIdx.x;
    if (p < NB*LS && tid < 256){
        const float4* s = (const float4*)(x + (size_t)p*4096 + xi*64 + xj);
        xr[0]=s[0]; xr[1]=s[1]; xr[2]=s[2]; xr[3]=s[3];
    }

    for (; p < NB*LS; p += gridDim.x){
        __syncthreads();                      // previous tile fully consumed
        if (tid < 256){                       // stage X (split) into smem
            const float* xf = (const float*)xr;
            uint32_t eb = (uint32_t)(xi * 72 + xj);
            #pragma unroll
            for (int k = 0; k < 8; k++){
                uint2 hl = split2(xf[2*k], xf[2*k+1]);
                *(uint32_t*)(sb + P1_XH + (eb + 2*k)*2) = hl.x;
                *(uint32_t*)(sb + P1_XL + (eb + 2*k)*2) = hl.y;
            }
        }
        __syncthreads();
        int pn = p + gridDim.x;               // prefetch next tile into regs
        if (pn < NB*LS && tid < 256){
            const float4* s = (const float4*)(x + (size_t)pn*4096 + xi*64 + xj);
            xr[0]=s[0]; xr[1]=s[1]; xr[2]=s[2]; xr[3]=s[3];
        }

        // ---- stage1: D[a 16rb..][j] = W1[g] @ X ----
        float D[8][4];
        #pragma unroll
        for (int t = 0; t < 8; t++){ D[t][0]=D[t][1]=D[t][2]=D[t][3]=0.0f; }
        #pragma unroll
        for (int kc = 0; kc < 4; kc++){
            uint32_t Ah[4], Al[4];
            ldm4(Ah, fraddr(w1hB, rb*16, kc*16, lane));
            ldm4(Al, fraddr(w1lB, rb*16, kc*16, lane));
            #pragma unroll
            for (int nb = 0; nb < 4; nb++){
                uint32_t Bh[4], Bl[4];
                ldm4t(Bh, fraddr(s0 + P1_XH, kc*16, nb*16, lane));
                ldm4t(Bl, fraddr(s0 + P1_XL, kc*16, nb*16, lane));
                mma16816(D[2*nb],   Ah, Bh[0], Bh[1]);
                mma16816(D[2*nb+1], Ah, Bh[2], Bh[3]);
                mma16816(D[2*nb],   Ah, Bl[0], Bl[1]);
                mma16816(D[2*nb+1], Ah, Bl[2], Bl[3]);
                mma16816(D[2*nb],   Al, Bh[0], Bh[1]);
                mma16816(D[2*nb+1], Al, Bh[2], Bh[3]);
            }
        }

        // ---- convert D -> stage2 A fragments (in registers, no smem) ----
        uint32_t A2h[4][4], A2l[4][4];
        #pragma unroll
        for (int kc = 0; kc < 4; kc++){
            uint2 p0 = split2(D[2*kc][0],   D[2*kc][1]);
            uint2 p1 = split2(D[2*kc][2],   D[2*kc][3]);
            uint2 p2 = split2(D[2*kc+1][0], D[2*kc+1][1]);
            uint2 p3 = split2(D[2*kc+1][2], D[2*kc+1][3]);
            A2h[kc][0]=p0.x; A2h[kc][1]=p1.x; A2h[kc][2]=p2.x; A2h[kc][3]=p3.x;
            A2l[kc][0]=p0.y; A2l[kc][1]=p1.y; A2l[kc][2]=p2.y; A2l[kc][3]=p3.y;
        }

        // ---- stage2: E = T @ W2t[g] ----
        float E[8][4];
        #pragma unroll
        for (int t = 0; t < 8; t++){ E[t][0]=E[t][1]=E[t][2]=E[t][3]=0.0f; }
        #pragma unroll
        for (int kc = 0; kc < 4; kc++){
            #pragma unroll
            for (int nb = 0; nb < 4; nb++){
                uint32_t Bh[4], Bl[4];
                ldm4t(Bh, fraddr(w2hB, kc*16, nb*16, lane));
                ldm4t(Bl, fraddr(w2lB, kc*16, nb*16, lane));
                mma16816(E[2*nb],   A2h[kc], Bh[0], Bh[1]);
                mma16816(E[2*nb+1], A2h[kc], Bh[2], Bh[3]);
                mma16816(E[2*nb],   A2h[kc], Bl[0], Bl[1]);
                mma16816(E[2*nb+1], A2h[kc], Bl[2], Bl[3]);
                mma16816(E[2*nb],   A2l[kc], Bh[0], Bh[1]);
                mma16816(E[2*nb+1], A2l[kc], Bh[2], Bh[3]);
            }
        }

        // ---- store E -> xg ----
        {
            const int n = p >> 7, l = p & 127;
            float* dst = xg + ((size_t)((l*3+g)*NB + n))*4096;
            const int r0 = rb*16 + (lane >> 2);
            const int cb = (lane & 3) * 2;
            #pragma unroll
            for (int nb = 0; nb < 4; nb++){
                #pragma unroll
                for (int hf = 0; hf < 2; hf++){
                    int t = 2*nb + hf;
                    int b = nb*16 + hf*8 + cb;
                    float* q = dst + r0*64 + b;
                    *(float2*)q             = make_float2(E[t][0], E[t][1]);
                    *(float2*)(q + 8*64)    = make_float2(E[t][2], E[t][3]);
                }
            }
        }
    }
}

// ---------------------------------------------------------------------------
// Phase 2: unchanged from round 4 (cluster-2, f32x2) — 1211us measured
// ---------------------------------------------------------------------------
__global__ void __launch_bounds__(384,1) __cluster_dims__(2,1,1) phase2_kernel(
    const float* __restrict__ Wu1, const float* __restrict__ Wu2,
    const float* __restrict__ xg, float* __restrict__ out)
{
    extern __shared__ float sm[];
    float* hs  = sm;
    float* W1t = sm + 4096;
    float* W2t = W1t + 6912;
    float* ts  = W2t + 13056;
    float* hgv = ts + 6912;
    float* xgs = hgv + 6144;

    const int tid = threadIdx.x;
    uint32_t rk; asm("mov.u32 %0, %%cluster_ctarank;" : "=r"(rk));
    const int n = blockIdx.x >> 1;
    const int A0 = (int)rk * 32;

    for (int idx = tid; idx < 6144; idx += 384){
        int g = idx/2048, r = idx&2047, al = r>>6, i = r&63;
        W1t[(g*64+i)*36+al] = Wu1[g*4096 + (A0+al)*64 + i];
    }
    for (int idx = tid; idx < 12288; idx += 384){
        int g = idx>>12, r = idx&4095, b = r>>6, j = r&63;
        W2t[(g*64+j)*68+b] = Wu2[idx];
    }
    for (int idx = tid; idx < 4096; idx += 384) hs[idx] = 0.0f;

    uint32_t hs_peer;
    { uint32_t hl = (uint32_t)__cvta_generic_to_shared(hs);
      asm("mapa.shared::cluster.u32 %0, %1, %2;" : "=r"(hs_peer) : "r"(hl), "r"(rk^1u)); }

    const int gg = tid/128, q = tid%128;
    const int al0 = (q>>4)*4, j0 = (q&15)*4;
    const int e_al = (tid>>3)&31, e_b0 = (tid&7)*8;

    float c[8];
    #pragma unroll
    for (int k=0;k<8;k++) c[k]=0.0f;

    __syncthreads();
    asm volatile("barrier.cluster.arrive.aligned;" ::: "memory");
    asm volatile("barrier.cluster.wait.aligned;" ::: "memory");

    for (int t = 0; t < LS; t++){
        #pragma unroll
        for (int k = 0; k < 4; k++){
            int cc = tid + 384*k;
            int gx = cc>>9, r = cc&511, row = r>>4, off = r&15;
            cpa16(xgs + gx*2048 + row*64 + off*4,
                  xg + ((size_t)((t*3+gx)*NB+n))*4096 + (A0+row)*64 + off*4);
        }
        asm volatile("cp.async.commit_group;");

        const float* w1 = W1t + gg*2304;
        float* tg = ts + gg*2304;
        uint64_t acc[4][2];
        #pragma unroll
        for (int aa=0; aa<4; aa++){ acc[aa][0]=0; acc[aa][1]=0; }
        #pragma unroll 4
        for (int i = 0; i < 64; i++){
            float4 wv = *(const float4*)(w1 + i*36 + al0);
            ulonglong2 hv = *(const ulonglong2*)(hs + i*64 + j0);
            uint64_t wp[4] = {pk2(wv.x,wv.x), pk2(wv.y,wv.y), pk2(wv.z,wv.z), pk2(wv.w,wv.w)};
            #pragma unroll
            for (int aa=0; aa<4; aa++){ fma2(acc[aa][0], wp[aa], hv.x); fma2(acc[aa][1], wp[aa], hv.y); }
        }
        {
            float f[4][4];
            #pragma unroll
            for (int aa=0; aa<4; aa++){ upk2(acc[aa][0], f[aa][0], f[aa][1]); upk2(acc[aa][1], f[aa][2], f[aa][3]); }
            #pragma unroll
            for (int jj=0; jj<4; jj++)
                *(float4*)(tg + (j0+jj)*36 + al0) = make_float4(f[0][jj], f[1][jj], f[2][jj], f[3][jj]);
        }
        __syncthreads();
        asm volatile("barrier.cluster.arrive.aligned;" ::: "memory");

        const float* w2 = W2t + gg*4352;
        uint64_t ac2[4][2];
        #pragma unroll
        for (int aa=0; aa<4; aa++){ ac2[aa][0]=0; ac2[aa][1]=0; }
        #pragma unroll 4
        for (int j = 0; j < 64; j++){
            float4 tv = *(const float4*)(tg + j*36 + al0);
            ulonglong2 wv = *(const ulonglong2*)(w2 + j*68 + j0);
            uint64_t tp[4] = {pk2(tv.x,tv.x), pk2(tv.y,tv.y), pk2(tv.z,tv.z), pk2(tv.w,tv.w)};
            #pragma unroll
            for (int aa=0; aa<4; aa++){ fma2(ac2[aa][0], tp[aa], wv.x); fma2(ac2[aa][1], tp[aa], wv.y); }
        }
        {
            float* hgd = hgv + gg*2048;
            #pragma unroll
            for (int aa=0; aa<4; aa++){
                ulonglong2 v; v.x = ac2[aa][0]; v.y = ac2[aa][1];
                *(ulonglong2*)(hgd + (al0+aa)*64 + j0) = v;
            }
        }
        asm volatile("cp.async.wait_group 0;");
        __syncthreads();
        asm volatile("barrier.cluster.wait.aligned;" ::: "memory");

        if (tid < 256){
            int base = e_al*64 + e_b0;
            float hv[8];
            #pragma unroll
            for (int k=0;k<8;k++){
                float z = sigm(hgv[base+k]      + xgs[base+k]);
                float r = sigm(hgv[2048+base+k] + xgs[2048+base+k]);
                float o = sigm(hgv[4096+base+k] + xgs[4096+base+k]);
                c[k] = r * (c[k] + z);
                hv[k] = o * sigm(c[k]);
            }
            float* od = out + ((size_t)(n*LS+t))*4096 + (A0+e_al)*64 + e_b0;
            *(float4*)(od)   = make_float4(hv[0],hv[1],hv[2],hv[3]);
            *(float4*)(od+4) = make_float4(hv[4],hv[5],hv[6],hv[7]);
            float* hl = hs + (A0+e_al)*64 + e_b0;
            *(float4*)(hl)   = make_float4(hv[0],hv[1],hv[2],hv[3]);
            *(float4*)(hl+4) = make_float4(hv[4],hv[5],hv[6],hv[7]);
            uint32_t rp = hs_peer + (uint32_t)(((A0+e_al)*64 + e_b0) << 2);
            #pragma unroll
            for (int k=0; k<8; k+=2){
                uint64_t pv = pk2(hv[k], hv[k+1]);
                asm volatile("st.shared::cluster.b64 [%0], %1;"
                             :: "r"(rp + (uint32_t)(k*4)), "l"(pv));
            }
        }
        asm volatile("barrier.cluster.arrive.aligned;" ::: "memory");
        asm volatile("barrier.cluster.wait.aligned;" ::: "memory");
    }

    for (int idx = tid; idx < 2048; idx += 384)
        out[(size_t)NB*LS*4096 + (size_t)n*4096 + A0*64 + idx] = hs[A0*64 + idx];
    if (tid < 256){
        float* cl = out + (size_t)NB*LS*4096 + (size_t)NB*4096
                        + (size_t)n*4096 + (A0+e_al)*64 + e_b0;
        *(float4*)(cl)   = make_float4(c[0],c[1],c[2],c[3]);
        *(float4*)(cl+4) = make_float4(c[4],c[5],c[6],c[7]);
    }
}

// ---------------------------------------------------------------------------
extern "C" void kernel_launch(void* const* d_in, const int* in_sizes, int n_in,
                              void* d_out, int out_size)
{
    const float* x   = (const float*)d_in[0];
    const float* Ww1 = (const float*)d_in[1];
    const float* Ww2 = (const float*)d_in[2];
    const float* Wu1 = (const float*)d_in[3];
    const float* Wu2 = (const float*)d_in[4];
    float* out = (float*)d_out;

    float* xg = nullptr;
    cudaGetSymbolAddress((void**)&xg, g_xg);

    const size_t smem2 = (4096 + 6912 + 13056 + 6912 + 6144 + 6144) * sizeof(float);

    cudaFuncSetAttribute(phase1_mma, cudaFuncAttributeMaxDynamicSharedMemorySize, (int)P1_BYTES);
    cudaFuncSetAttribute(phase2_kernel, cudaFuncAttributeMaxDynamicSharedMemorySize, (int)smem2);

    phase1_mma<<<148, 384, P1_BYTES>>>(x, Ww1, Ww2, xg);
    phase2_kernel<<<2 * NB, 384, smem2>>>(Wu1, Wu2, xg, out);
}

// round 7
// speedup vs baseline: 3.1816x; 1.1716x over previous
#include <cuda_runtime.h>
#include <cuda_bf16.h>
#include <cstdint>
#include <cstddef>

#define NB 64
#define LS 128

__device__ float g_xg[(size_t)LS*3*NB*4096];

__device__ __forceinline__ float sigm(float x){ return 1.0f/(1.0f+__expf(-x)); }
__device__ __forceinline__ void cpa16(void* dst, const float* src){
    asm volatile("cp.async.ca.shared.global [%0], [%1], 16;"
                 :: "r"((uint32_t)__cvta_generic_to_shared(dst)), "l"(src)); }
__device__ __forceinline__ uint32_t smem_u32(const void* p){
    uint32_t a; asm("{ .reg .u64 t; cvta.to.shared.u64 t, %1; cvt.u32.u64 %0, t; }"
                    : "=r"(a) : "l"(p)); return a; }

// split pair (f0,f1) -> hi bf16x2, lo-residual bf16x2
__device__ __forceinline__ uint2 split2(float f0, float f1){
    __nv_bfloat162 h2 = __floats2bfloat162_rn(f0, f1);
    uint32_t u = *(uint32_t*)&h2;
    float b0 = __uint_as_float(u << 16);
    float b1 = __uint_as_float(u & 0xffff0000u);
    __nv_bfloat162 l2 = __floats2bfloat162_rn(f0 - b0, f1 - b1);
    uint2 r; r.x = u; r.y = *(uint32_t*)&l2;
    return r;
}
__device__ __forceinline__ void ldm4(uint32_t* r, uint32_t addr){
    asm volatile("ldmatrix.sync.aligned.m8n8.x4.shared.b16 {%0,%1,%2,%3}, [%4];"
        : "=r"(r[0]),"=r"(r[1]),"=r"(r[2]),"=r"(r[3]) : "r"(addr));
}
__device__ __forceinline__ void ldm4t(uint32_t* r, uint32_t addr){
    asm volatile("ldmatrix.sync.aligned.m8n8.x4.trans.shared.b16 {%0,%1,%2,%3}, [%4];"
        : "=r"(r[0]),"=r"(r[1]),"=r"(r[2]),"=r"(r[3]) : "r"(addr));
}
__device__ __forceinline__ void mma16816(float* d, const uint32_t* a, uint32_t b0, uint32_t b1){
    asm volatile("mma.sync.aligned.m16n8k16.row.col.f32.bf16.bf16.f32 "
        "{%0,%1,%2,%3}, {%4,%5,%6,%7}, {%8,%9}, {%0,%1,%2,%3};"
        : "+f"(d[0]),"+f"(d[1]),"+f"(d[2]),"+f"(d[3])
        : "r"(a[0]),"r"(a[1]),"r"(a[2]),"r"(a[3]), "r"(b0),"r"(b1));
}
// lane address into 16x16 block of row-major bf16 array, row stride 72 elems
__device__ __forceinline__ uint32_t fraddr(uint32_t base, int row0, int col0, int lane){
    int grp = lane >> 3, lr = lane & 7;
    int row = row0 + lr + (grp & 1) * 8;
    int col = col0 + (grp >> 1) * 8;
    return base + (uint32_t)(row * 72 + col) * 2u;
}

// ===================== Phase 1 (unchanged, verified round 6) =====================
#define P1_XH   0u
#define P1_XL   9216u
#define P1_W1H  18432u
#define P1_W1L  46080u
#define P1_W2H  73728u
#define P1_W2L  101376u
#define P1_BYTES 129024u

__global__ void __launch_bounds__(384,1) phase1_mma(
    const float* __restrict__ x, const float* __restrict__ Ww1,
    const float* __restrict__ Ww2, float* __restrict__ xg)
{
    extern __shared__ char sb[];
    const uint32_t s0 = smem_u32(sb);
    const int tid = threadIdx.x, wid = tid >> 5, lane = tid & 31;

    if (tid < 192){
        const int g = tid >> 6, row = tid & 63;
        float w[64];
        #pragma unroll
        for (int q = 0; q < 16; q++)
            ((float4*)w)[q] = ((const float4*)(Ww1 + tid * 64))[q];
        uint32_t eb = (uint32_t)(g * 4608 + row * 72);
        #pragma unroll
        for (int k = 0; k < 32; k++){
            uint2 hl = split2(w[2*k], w[2*k+1]);
            *(uint32_t*)(sb + P1_W1H + (eb + 2*k)*2) = hl.x;
            *(uint32_t*)(sb + P1_W1L + (eb + 2*k)*2) = hl.y;
        }
        #pragma unroll 4
        for (int b = 0; b < 64; b++) w[b] = Ww2[g * 4096 + b * 64 + row];
        #pragma unroll
        for (int k = 0; k < 32; k++){
            uint2 hl = split2(w[2*k], w[2*k+1]);
            *(uint32_t*)(sb + P1_W2H + (eb + 2*k)*2) = hl.x;
            *(uint32_t*)(sb + P1_W2L + (eb + 2*k)*2) = hl.y;
        }
    }

    const int g  = wid >> 2;
    const int rb = wid & 3;
    const uint32_t w1hB = s0 + P1_W1H + (uint32_t)g * 9216u;
    const uint32_t w1lB = s0 + P1_W1L + (uint32_t)g * 9216u;
    const uint32_t w2hB = s0 + P1_W2H + (uint32_t)g * 9216u;
    const uint32_t w2lB = s0 + P1_W2L + (uint32_t)g * 9216u;

    float4 xr[4];
    const int xi = tid >> 2, xj = (tid & 3) * 16;

    int p = blockIdx.x;
    if (p < NB*LS && tid < 256){
        const float4* s = (const float4*)(x + (size_t)p*4096 + xi*64 + xj);
        xr[0]=s[0]; xr[1]=s[1]; xr[2]=s[2]; xr[3]=s[3];
    }

    for (; p < NB*LS; p += gridDim.x){
        __syncthreads();
        if (tid < 256){
            const float* xf = (const float*)xr;
            uint32_t eb = (uint32_t)(xi * 72 + xj);
            #pragma unroll
            for (int k = 0; k < 8; k++){
                uint2 hl = split2(xf[2*k], xf[2*k+1]);
                *(uint32_t*)(sb + P1_XH + (eb + 2*k)*2) = hl.x;
                *(uint32_t*)(sb + P1_XL + (eb + 2*k)*2) = hl.y;
            }
        }
        __syncthreads();
        int pn = p + gridDim.x;
        if (pn < NB*LS && tid < 256){
            const float4* s = (const float4*)(x + (size_t)pn*4096 + xi*64 + xj);
            xr[0]=s[0]; xr[1]=s[1]; xr[2]=s[2]; xr[3]=s[3];
        }

        float D[8][4];
        #pragma unroll
        for (int t = 0; t < 8; t++){ D[t][0]=D[t][1]=D[t][2]=D[t][3]=0.0f; }
        #pragma unroll
        for (int kc = 0; kc < 4; kc++){
            uint32_t Ah[4], Al[4];
            ldm4(Ah, fraddr(w1hB, rb*16, kc*16, lane));
            ldm4(Al, fraddr(w1lB, rb*16, kc*16, lane));
            #pragma unroll
            for (int nb = 0; nb < 4; nb++){
                uint32_t Bh[4], Bl[4];
                ldm4t(Bh, fraddr(s0 + P1_XH, kc*16, nb*16, lane));
                ldm4t(Bl, fraddr(s0 + P1_XL, kc*16, nb*16, lane));
                mma16816(D[2*nb],   Ah, Bh[0], Bh[1]);
                mma16816(D[2*nb+1], Ah, Bh[2], Bh[3]);
                mma16816(D[2*nb],   Ah, Bl[0], Bl[1]);
                mma16816(D[2*nb+1], Ah, Bl[2], Bl[3]);
                mma16816(D[2*nb],   Al, Bh[0], Bh[1]);
                mma16816(D[2*nb+1], Al, Bh[2], Bh[3]);
            }
        }

        uint32_t A2h[4][4], A2l[4][4];
        #pragma unroll
        for (int kc = 0; kc < 4; kc++){
            uint2 p0 = split2(D[2*kc][0],   D[2*kc][1]);
            uint2 p1 = split2(D[2*kc][2],   D[2*kc][3]);
            uint2 p2 = split2(D[2*kc+1][0], D[2*kc+1][1]);
            uint2 p3 = split2(D[2*kc+1][2], D[2*kc+1][3]);
            A2h[kc][0]=p0.x; A2h[kc][1]=p1.x; A2h[kc][2]=p2.x; A2h[kc][3]=p3.x;
            A2l[kc][0]=p0.y; A2l[kc][1]=p1.y; A2l[kc][2]=p2.y; A2l[kc][3]=p3.y;
        }

        float E[8][4];
        #pragma unroll
        for (int t = 0; t < 8; t++){ E[t][0]=E[t][1]=E[t][2]=E[t][3]=0.0f; }
        #pragma unroll
        for (int kc = 0; kc < 4; kc++){
            #pragma unroll
            for (int nb = 0; nb < 4; nb++){
                uint32_t Bh[4], Bl[4];
                ldm4t(Bh, fraddr(w2hB, kc*16, nb*16, lane));
                ldm4t(Bl, fraddr(w2lB, kc*16, nb*16, lane));
                mma16816(E[2*nb],   A2h[kc], Bh[0], Bh[1]);
                mma16816(E[2*nb+1], A2h[kc], Bh[2], Bh[3]);
                mma16816(E[2*nb],   A2h[kc], Bl[0], Bl[1]);
                mma16816(E[2*nb+1], A2h[kc], Bl[2], Bl[3]);
                mma16816(E[2*nb],   A2l[kc], Bh[0], Bh[1]);
                mma16816(E[2*nb+1], A2l[kc], Bh[2], Bh[3]);
            }
        }

        {
            const int n = p >> 7, l = p & 127;
            float* dst = xg + ((size_t)((l*3+g)*NB + n))*4096;
            const int r0 = rb*16 + (lane >> 2);
            const int cb = (lane & 3) * 2;
            #pragma unroll
            for (int nb = 0; nb < 4; nb++){
                #pragma unroll
                for (int hf = 0; hf < 2; hf++){
                    int t = 2*nb + hf;
                    int b = nb*16 + hf*8 + cb;
                    float* q = dst + r0*64 + b;
                    *(float2*)q          = make_float2(E[t][0], E[t][1]);
                    *(float2*)(q + 8*64) = make_float2(E[t][2], E[t][3]);
                }
            }
        }
    }
}

// ===================== Phase 2 (mma.sync, one CTA per n) =====================
// smem bytes: HS_H 0 (9216) | HS_L 9216 | W2H 18432 (27648) | W2L 46080 (27648)
//             HGV 73728 (fp32 3*64*64 = 49152) | XGS 122880 (2 x 49152)
#define P2_HSH  0u
#define P2_HSL  9216u
#define P2_W2H  18432u
#define P2_W2L  46080u
#define P2_HGV  73728u
#define P2_XGS  122880u
#define P2_BYTES 221184u

__global__ void __launch_bounds__(384,1) phase2_mma(
    const float* __restrict__ Wu1, const float* __restrict__ Wu2,
    const float* __restrict__ xg, float* __restrict__ out)
{
    extern __shared__ char sb[];
    const uint32_t s0 = smem_u32(sb);
    float* smf = (float*)sb;
    const int tid = threadIdx.x, wid = tid >> 5, lane = tid & 31;
    const int n = blockIdx.x;
    const int HGVf = 18432, XGSf = 30720;   // float indices

    // init: Wu2t split (W2t[g][j][b] = Wu2[g][b][j])
    if (tid < 192){
        const int g = tid >> 6, j = tid & 63;
        float w[64];
        #pragma unroll 4
        for (int b = 0; b < 64; b++) w[b] = Wu2[g*4096 + b*64 + j];
        uint32_t eb = (uint32_t)((g*64 + j) * 72);
        #pragma unroll
        for (int k = 0; k < 32; k++){
            uint2 hl = split2(w[2*k], w[2*k+1]);
            *(uint32_t*)(sb + P2_W2H + (eb + 2*k)*2) = hl.x;
            *(uint32_t*)(sb + P2_W2L + (eb + 2*k)*2) = hl.y;
        }
    }
    // Wu1 split into temp (XGS area: hi at XGS, lo at XGS+27648)
    if (tid < 192){
        const int g = tid >> 6, a = tid & 63;
        float w[64];
        #pragma unroll
        for (int q = 0; q < 16; q++)
            ((float4*)w)[q] = ((const float4*)(Wu1 + (g*64 + a)*64))[q];
        uint32_t eb = (uint32_t)((g*64 + a) * 72);
        #pragma unroll
        for (int k = 0; k < 32; k++){
            uint2 hl = split2(w[2*k], w[2*k+1]);
            *(uint32_t*)(sb + P2_XGS + (eb + 2*k)*2) = hl.x;
            *(uint32_t*)(sb + P2_XGS + 27648u + (eb + 2*k)*2) = hl.y;
        }
    }
    // zero h (hi+lo, 18432 B)
    for (int i = tid; i < 4608; i += 384) ((uint32_t*)sb)[i] = 0;
    __syncthreads();

    // preload Wu1 A-fragments (constant over t)
    const int g = wid >> 2, rb = wid & 3;
    uint32_t Ah[4][4], Al[4][4];
    #pragma unroll
    for (int kc = 0; kc < 4; kc++){
        ldm4(Ah[kc], fraddr(s0 + P2_XGS + (uint32_t)g*9216u, rb*16, kc*16, lane));
        ldm4(Al[kc], fraddr(s0 + P2_XGS + 27648u + (uint32_t)g*9216u, rb*16, kc*16, lane));
    }
    __syncthreads();   // temp reads done; XGS reusable

    const uint32_t w2hB = s0 + P2_W2H + (uint32_t)g * 9216u;
    const uint32_t w2lB = s0 + P2_W2L + (uint32_t)g * 9216u;

    float cst[11];
    #pragma unroll
    for (int it = 0; it < 11; it++) cst[it] = 0.0f;

    // prefetch xg[0] into buf 0
    {
        #pragma unroll
        for (int k = 0; k < 8; k++){
            int idx = tid + 384*k;              // < 3072 chunks of 16B
            int gx = idx >> 10, rem = idx & 1023;
            cpa16(smf + XGSf + gx*4096 + rem*4,
                  xg + ((size_t)((0*3 + gx)*NB + n))*4096 + rem*4);
        }
        asm volatile("cp.async.commit_group;");
    }

    int buf = 0;
    for (int t = 0; t < LS; t++){
        if (t + 1 < LS){
            #pragma unroll
            for (int k = 0; k < 8; k++){
                int idx = tid + 384*k;
                int gx = idx >> 10, rem = idx & 1023;
                cpa16(smf + XGSf + (buf^1)*12288 + gx*4096 + rem*4,
                      xg + ((size_t)(((t+1)*3 + gx)*NB + n))*4096 + rem*4);
            }
        }
        asm volatile("cp.async.commit_group;");

        // stage1: T = Wu1[g] @ h
        float D[8][4];
        #pragma unroll
        for (int q = 0; q < 8; q++){ D[q][0]=D[q][1]=D[q][2]=D[q][3]=0.0f; }
        #pragma unroll
        for (int kc = 0; kc < 4; kc++){
            #pragma unroll
            for (int nb = 0; nb < 4; nb++){
                uint32_t Bh[4], Bl[4];
                ldm4t(Bh, fraddr(s0 + P2_HSH, kc*16, nb*16, lane));
                ldm4t(Bl, fraddr(s0 + P2_HSL, kc*16, nb*16, lane));
                mma16816(D[2*nb],   Ah[kc], Bh[0], Bh[1]);
                mma16816(D[2*nb+1], Ah[kc], Bh[2], Bh[3]);
                mma16816(D[2*nb],   Ah[kc], Bl[0], Bl[1]);
                mma16816(D[2*nb+1], Ah[kc], Bl[2], Bl[3]);
                mma16816(D[2*nb],   Al[kc], Bh[0], Bh[1]);
                mma16816(D[2*nb+1], Al[kc], Bh[2], Bh[3]);
            }
        }
        // repack D -> A2 fragments
        uint32_t A2h[4][4], A2l[4][4];
        #pragma unroll
        for (int kc = 0; kc < 4; kc++){
            uint2 p0 = split2(D[2*kc][0],   D[2*kc][1]);
            uint2 p1 = split2(D[2*kc][2],   D[2*kc][3]);
            uint2 p2 = split2(D[2*kc+1][0], D[2*kc+1][1]);
            uint2 p3 = split2(D[2*kc+1][2], D[2*kc+1][3]);
            A2h[kc][0]=p0.x; A2h[kc][1]=p1.x; A2h[kc][2]=p2.x; A2h[kc][3]=p3.x;
            A2l[kc][0]=p0.y; A2l[kc][1]=p1.y; A2l[kc][2]=p2.y; A2l[kc][3]=p3.y;
        }
        // stage2: hg = T @ Wu2t[g]
        float E[8][4];
        #pragma unroll
        for (int q = 0; q < 8; q++){ E[q][0]=E[q][1]=E[q][2]=E[q][3]=0.0f; }
        #pragma unroll
        for (int kc = 0; kc < 4; kc++){
            #pragma unroll
            for (int nb = 0; nb < 4; nb++){
                uint32_t Bh[4], Bl[4];
                ldm4t(Bh, fraddr(w2hB, kc*16, nb*16, lane));
                ldm4t(Bl, fraddr(w2lB, kc*16, nb*16, lane));
                mma16816(E[2*nb],   A2h[kc], Bh[0], Bh[1]);
                mma16816(E[2*nb+1], A2h[kc], Bh[2], Bh[3]);
                mma16816(E[2*nb],   A2h[kc], Bl[0], Bl[1]);
                mma16816(E[2*nb+1], A2h[kc], Bl[2], Bl[3]);
                mma16816(E[2*nb],   A2l[kc], Bh[0], Bh[1]);
                mma16816(E[2*nb+1], A2l[kc], Bh[2], Bh[3]);
            }
        }
        // store E (fp32) -> HGV
        {
            float* dst = smf + HGVf + g*4096;
            const int r0 = rb*16 + (lane >> 2);
            const int cb = (lane & 3) * 2;
            #pragma unroll
            for (int nb = 0; nb < 4; nb++){
                #pragma unroll
                for (int hf = 0; hf < 2; hf++){
                    int q = 2*nb + hf;
                    int b = nb*16 + hf*8 + cb;
                    float* d2 = dst + r0*64 + b;
                    *(float2*)d2          = make_float2(E[q][0], E[q][1]);
                    *(float2*)(d2 + 8*64) = make_float2(E[q][2], E[q][3]);
                }
            }
        }
        asm volatile("cp.async.wait_group 1;");
        __syncthreads();

        // epilogue: gates, c/h update, h back to smem (bf16 split), outs to global
        #pragma unroll
        for (int it = 0; it < 11; it++){
            int e = tid + it*384;
            if (e < 4096){
                const int xb = XGSf + buf*12288;
                float z = sigm(smf[HGVf + e]        + smf[xb + e]);
                float r = sigm(smf[HGVf + 4096 + e] + smf[xb + 4096 + e]);
                float o = sigm(smf[HGVf + 8192 + e] + smf[xb + 8192 + e]);
                cst[it] = r * (cst[it] + z);
                float hv = o * sigm(cst[it]);
                out[((size_t)(n*LS + t))*4096 + e] = hv;
                if (t == LS-1)
                    out[(size_t)NB*LS*4096 + (size_t)n*4096 + e] = hv;
                __nv_bfloat16 bh = __float2bfloat16(hv);
                float res = hv - __bfloat162float(bh);
                __nv_bfloat16 bl = __float2bfloat16(res);
                uint32_t ho = (uint32_t)((e >> 6)*72 + (e & 63)) * 2u;
                *(uint16_t*)(sb + P2_HSH + ho) = __bfloat16_as_ushort(bh);
                *(uint16_t*)(sb + P2_HSL + ho) = __bfloat16_as_ushort(bl);
            }
        }
        __syncthreads();
        buf ^= 1;
    }

    // c_last
    #pragma unroll
    for (int it = 0; it < 11; it++){
        int e = tid + it*384;
        if (e < 4096)
            out[(size_t)NB*LS*4096 + (size_t)NB*4096 + (size_t)n*4096 + e] = cst[it];
    }
}

// ---------------------------------------------------------------------------
extern "C" void kernel_launch(void* const* d_in, const int* in_sizes, int n_in,
                              void* d_out, int out_size)
{
    const float* x   = (const float*)d_in[0];
    const float* Ww1 = (const float*)d_in[1];
    const float* Ww2 = (const float*)d_in[2];
    const float* Wu1 = (const float*)d_in[3];
    const float* Wu2 = (const float*)d_in[4];
    float* out = (float*)d_out;

    float* xg = nullptr;
    cudaGetSymbolAddress((void**)&xg, g_xg);

    cudaFuncSetAttribute(phase1_mma, cudaFuncAttributeMaxDynamicSharedMemorySize, (int)P1_BYTES);
    cudaFuncSetAttribute(phase2_mma, cudaFuncAttributeMaxDynamicSharedMemorySize, (int)P2_BYTES);

    phase1_mma<<<148, 384, P1_BYTES>>>(x, Ww1, Ww2, xg);
    phase2_mma<<<NB, 384, P2_BYTES>>>(Wu1, Wu2, xg, out);
}

// round 8
// speedup vs baseline: 3.8317x; 1.2043x over previous
#include <cuda_runtime.h>
#include <cuda_bf16.h>
#include <cstdint>
#include <cstddef>

#define NB 64
#define LS 128

__device__ float g_xg[(size_t)LS*3*NB*4096];

__device__ __forceinline__ float sigm(float x){ return 1.0f/(1.0f+__expf(-x)); }
__device__ __forceinline__ void cpa16(void* dst, const float* src){
    asm volatile("cp.async.ca.shared.global [%0], [%1], 16;"
                 :: "r"((uint32_t)__cvta_generic_to_shared(dst)), "l"(src)); }
__device__ __forceinline__ uint32_t smem_u32(const void* p){
    uint32_t a; asm("{ .reg .u64 t; cvta.to.shared.u64 t, %1; cvt.u32.u64 %0, t; }"
                    : "=r"(a) : "l"(p)); return a; }

// split pair (f0,f1) -> hi bf16x2, lo-residual bf16x2
__device__ __forceinline__ uint2 split2(float f0, float f1){
    __nv_bfloat162 h2 = __floats2bfloat162_rn(f0, f1);
    uint32_t u = *(uint32_t*)&h2;
    float b0 = __uint_as_float(u << 16);
    float b1 = __uint_as_float(u & 0xffff0000u);
    __nv_bfloat162 l2 = __floats2bfloat162_rn(f0 - b0, f1 - b1);
    uint2 r; r.x = u; r.y = *(uint32_t*)&l2;
    return r;
}
__device__ __forceinline__ void ldm4(uint32_t* r, uint32_t addr){
    asm volatile("ldmatrix.sync.aligned.m8n8.x4.shared.b16 {%0,%1,%2,%3}, [%4];"
        : "=r"(r[0]),"=r"(r[1]),"=r"(r[2]),"=r"(r[3]) : "r"(addr));
}
__device__ __forceinline__ void ldm4t(uint32_t* r, uint32_t addr){
    asm volatile("ldmatrix.sync.aligned.m8n8.x4.trans.shared.b16 {%0,%1,%2,%3}, [%4];"
        : "=r"(r[0]),"=r"(r[1]),"=r"(r[2]),"=r"(r[3]) : "r"(addr));
}
__device__ __forceinline__ void mma16816(float* d, const uint32_t* a, uint32_t b0, uint32_t b1){
    asm volatile("mma.sync.aligned.m16n8k16.row.col.f32.bf16.bf16.f32 "
        "{%0,%1,%2,%3}, {%4,%5,%6,%7}, {%8,%9}, {%0,%1,%2,%3};"
        : "+f"(d[0]),"+f"(d[1]),"+f"(d[2]),"+f"(d[3])
        : "r"(a[0]),"r"(a[1]),"r"(a[2]),"r"(a[3]), "r"(b0),"r"(b1));
}
// lane address into 16x16 block of row-major bf16 array, row stride 72 elems
__device__ __forceinline__ uint32_t fraddr(uint32_t base, int row0, int col0, int lane){
    int grp = lane >> 3, lr = lane & 7;
    int row = row0 + lr + (grp & 1) * 8;
    int col = col0 + (grp >> 1) * 8;
    return base + (uint32_t)(row * 72 + col) * 2u;
}

// ===================== Phase 1 (unchanged, verified round 6) =====================
#define P1_XH   0u
#define P1_XL   9216u
#define P1_W1H  18432u
#define P1_W1L  46080u
#define P1_W2H  73728u
#define P1_W2L  101376u
#define P1_BYTES 129024u

__global__ void __launch_bounds__(384,1) phase1_mma(
    const float* __restrict__ x, const float* __restrict__ Ww1,
    const float* __restrict__ Ww2, float* __restrict__ xg)
{
    extern __shared__ char sb[];
    const uint32_t s0 = smem_u32(sb);
    const int tid = threadIdx.x, wid = tid >> 5, lane = tid & 31;

    if (tid < 192){
        const int g = tid >> 6, row = tid & 63;
        float w[64];
        #pragma unroll
        for (int q = 0; q < 16; q++)
            ((float4*)w)[q] = ((const float4*)(Ww1 + tid * 64))[q];
        uint32_t eb = (uint32_t)(g * 4608 + row * 72);
        #pragma unroll
        for (int k = 0; k < 32; k++){
            uint2 hl = split2(w[2*k], w[2*k+1]);
            *(uint32_t*)(sb + P1_W1H + (eb + 2*k)*2) = hl.x;
            *(uint32_t*)(sb + P1_W1L + (eb + 2*k)*2) = hl.y;
        }
        #pragma unroll 4
        for (int b = 0; b < 64; b++) w[b] = Ww2[g * 4096 + b * 64 + row];
        #pragma unroll
        for (int k = 0; k < 32; k++){
            uint2 hl = split2(w[2*k], w[2*k+1]);
            *(uint32_t*)(sb + P1_W2H + (eb + 2*k)*2) = hl.x;
            *(uint32_t*)(sb + P1_W2L + (eb + 2*k)*2) = hl.y;
        }
    }

    const int g  = wid >> 2;
    const int rb = wid & 3;
    const uint32_t w1hB = s0 + P1_W1H + (uint32_t)g * 9216u;
    const uint32_t w1lB = s0 + P1_W1L + (uint32_t)g * 9216u;
    const uint32_t w2hB = s0 + P1_W2H + (uint32_t)g * 9216u;
    const uint32_t w2lB = s0 + P1_W2L + (uint32_t)g * 9216u;

    float4 xr[4];
    const int xi = tid >> 2, xj = (tid & 3) * 16;

    int p = blockIdx.x;
    if (p < NB*LS && tid < 256){
        const float4* s = (const float4*)(x + (size_t)p*4096 + xi*64 + xj);
        xr[0]=s[0]; xr[1]=s[1]; xr[2]=s[2]; xr[3]=s[3];
    }

    for (; p < NB*LS; p += gridDim.x){
        __syncthreads();
        if (tid < 256){
            const float* xf = (const float*)xr;
            uint32_t eb = (uint32_t)(xi * 72 + xj);
            #pragma unroll
            for (int k = 0; k < 8; k++){
                uint2 hl = split2(xf[2*k], xf[2*k+1]);
                *(uint32_t*)(sb + P1_XH + (eb + 2*k)*2) = hl.x;
                *(uint32_t*)(sb + P1_XL + (eb + 2*k)*2) = hl.y;
            }
        }
        __syncthreads();
        int pn = p + gridDim.x;
        if (pn < NB*LS && tid < 256){
            const float4* s = (const float4*)(x + (size_t)pn*4096 + xi*64 + xj);
            xr[0]=s[0]; xr[1]=s[1]; xr[2]=s[2]; xr[3]=s[3];
        }

        float D[8][4];
        #pragma unroll
        for (int t = 0; t < 8; t++){ D[t][0]=D[t][1]=D[t][2]=D[t][3]=0.0f; }
        #pragma unroll
        for (int kc = 0; kc < 4; kc++){
            uint32_t Ah[4], Al[4];
            ldm4(Ah, fraddr(w1hB, rb*16, kc*16, lane));
            ldm4(Al, fraddr(w1lB, rb*16, kc*16, lane));
            #pragma unroll
            for (int nb = 0; nb < 4; nb++){
                uint32_t Bh[4], Bl[4];
                ldm4t(Bh, fraddr(s0 + P1_XH, kc*16, nb*16, lane));
                ldm4t(Bl, fraddr(s0 + P1_XL, kc*16, nb*16, lane));
                mma16816(D[2*nb],   Ah, Bh[0], Bh[1]);
                mma16816(D[2*nb+1], Ah, Bh[2], Bh[3]);
                mma16816(D[2*nb],   Ah, Bl[0], Bl[1]);
                mma16816(D[2*nb+1], Ah, Bl[2], Bl[3]);
                mma16816(D[2*nb],   Al, Bh[0], Bh[1]);
                mma16816(D[2*nb+1], Al, Bh[2], Bh[3]);
            }
        }

        uint32_t A2h[4][4], A2l[4][4];
        #pragma unroll
        for (int kc = 0; kc < 4; kc++){
            uint2 p0 = split2(D[2*kc][0],   D[2*kc][1]);
            uint2 p1 = split2(D[2*kc][2],   D[2*kc][3]);
            uint2 p2 = split2(D[2*kc+1][0], D[2*kc+1][1]);
            uint2 p3 = split2(D[2*kc+1][2], D[2*kc+1][3]);
            A2h[kc][0]=p0.x; A2h[kc][1]=p1.x; A2h[kc][2]=p2.x; A2h[kc][3]=p3.x;
            A2l[kc][0]=p0.y; A2l[kc][1]=p1.y; A2l[kc][2]=p2.y; A2l[kc][3]=p3.y;
        }

        float E[8][4];
        #pragma unroll
        for (int t = 0; t < 8; t++){ E[t][0]=E[t][1]=E[t][2]=E[t][3]=0.0f; }
        #pragma unroll
        for (int kc = 0; kc < 4; kc++){
            #pragma unroll
            for (int nb = 0; nb < 4; nb++){
                uint32_t Bh[4], Bl[4];
                ldm4t(Bh, fraddr(w2hB, kc*16, nb*16, lane));
                ldm4t(Bl, fraddr(w2lB, kc*16, nb*16, lane));
                mma16816(E[2*nb],   A2h[kc], Bh[0], Bh[1]);
                mma16816(E[2*nb+1], A2h[kc], Bh[2], Bh[3]);
                mma16816(E[2*nb],   A2h[kc], Bl[0], Bl[1]);
                mma16816(E[2*nb+1], A2h[kc], Bl[2], Bl[3]);
                mma16816(E[2*nb],   A2l[kc], Bh[0], Bh[1]);
                mma16816(E[2*nb+1], A2l[kc], Bh[2], Bh[3]);
            }
        }

        {
            const int n = p >> 7, l = p & 127;
            float* dst = xg + ((size_t)((l*3+g)*NB + n))*4096;
            const int r0 = rb*16 + (lane >> 2);
            const int cb = (lane & 3) * 2;
            #pragma unroll
            for (int nb = 0; nb < 4; nb++){
                #pragma unroll
                for (int hf = 0; hf < 2; hf++){
                    int t = 2*nb + hf;
                    int b = nb*16 + hf*8 + cb;
                    float* q = dst + r0*64 + b;
                    *(float2*)q          = make_float2(E[t][0], E[t][1]);
                    *(float2*)(q + 8*64) = make_float2(E[t][2], E[t][3]);
                }
            }
        }
    }
}

// ===================== Phase 2 (mma.sync, cluster-2 per n) =====================
// CTA rank rk owns a-rows [32rk, 32rk+32). Warp = (g, rb16, jhalf).
// smem: HSH 0 (9216) | HSL 9216 | W2H 18432 (27648) | W2L 46080 (27648) |
//       EP 73728 (2*3*32*64 fp32 = 49152) | XGS 122880 (2 bufs * 6144 fp32 = 49152)
#define Q2_HSH 0u
#define Q2_HSL 9216u
#define Q2_W2H 18432u
#define Q2_W2L 46080u
#define Q2_EP  73728u
#define Q2_XGS 122880u
#define Q2_BYTES 172032u

__global__ void __launch_bounds__(384,1) __cluster_dims__(2,1,1) phase2_mma(
    const float* __restrict__ Wu1, const float* __restrict__ Wu2,
    const float* __restrict__ xg, float* __restrict__ out)
{
    extern __shared__ char sb[];
    const uint32_t s0 = smem_u32(sb);
    float* smf = (float*)sb;
    const int tid = threadIdx.x, wid = tid >> 5, lane = tid & 31;
    uint32_t rk; asm("mov.u32 %0, %%cluster_ctarank;" : "=r"(rk));
    const int n  = blockIdx.x >> 1;
    const int A0 = (int)rk * 32;
    const int EPf = 18432, XGSf = 30720;     // float indices

    // ---- init: Wu2t split (full, both CTAs) ----
    if (tid < 192){
        const int g = tid >> 6, j = tid & 63;
        float w[64];
        #pragma unroll 4
        for (int b = 0; b < 64; b++) w[b] = Wu2[g*4096 + b*64 + j];
        uint32_t eb = (uint32_t)((g*64 + j) * 72);
        #pragma unroll
        for (int k = 0; k < 32; k++){
            uint2 hl = split2(w[2*k], w[2*k+1]);
            *(uint32_t*)(sb + Q2_W2H + (eb + 2*k)*2) = hl.x;
            *(uint32_t*)(sb + Q2_W2L + (eb + 2*k)*2) = hl.y;
        }
    }
    // ---- Wu1 own 32 rows per gate, split into temp (XGS area) ----
    // hi at XGS, lo at XGS + 13824 bytes (3*32*72*2)
    if (tid < 96){
        const int g = tid >> 5, a = tid & 31;
        float w[64];
        #pragma unroll
        for (int q = 0; q < 16; q++)
            ((float4*)w)[q] = ((const float4*)(Wu1 + (size_t)(g*64 + A0 + a)*64))[q];
        uint32_t eb = (uint32_t)((g*32 + a) * 72);
        #pragma unroll
        for (int k = 0; k < 32; k++){
            uint2 hl = split2(w[2*k], w[2*k+1]);
            *(uint32_t*)(sb + Q2_XGS + (eb + 2*k)*2) = hl.x;
            *(uint32_t*)(sb + Q2_XGS + 13824u + (eb + 2*k)*2) = hl.y;
        }
    }
    // zero h (hi+lo)
    for (int i = tid; i < 4608; i += 384) ((uint32_t*)sb)[i] = 0;
    __syncthreads();

    // ---- warp task + A-fragment preload (constant over t) ----
    const int g  = wid >> 2;          // 0..2
    const int rb = (wid >> 1) & 1;    // rowblock16 within own 32 rows
    const int jh = wid & 1;           // j half
    uint32_t Ah[4][4], Al[4][4];
    #pragma unroll
    for (int kc = 0; kc < 4; kc++){
        ldm4(Ah[kc], fraddr(s0 + Q2_XGS + (uint32_t)g*4608u, rb*16, kc*16, lane));
        ldm4(Al[kc], fraddr(s0 + Q2_XGS + 13824u + (uint32_t)g*4608u, rb*16, kc*16, lane));
    }
    __syncthreads();   // temp reads done; XGS reusable

    const uint32_t w2hB = s0 + Q2_W2H + (uint32_t)g * 9216u;
    const uint32_t w2lB = s0 + Q2_W2L + (uint32_t)g * 9216u;

    // epilogue mapping: 256 threads, 8 cols each over own 32 rows
    const int e_r = tid >> 3, e_c = (tid & 7) * 8;
    float cst[8];
    #pragma unroll
    for (int k = 0; k < 8; k++) cst[k] = 0.0f;

    uint32_t hs_peerH, hs_peerL;
    { uint32_t hl_ = s0 + Q2_HSH;
      asm("mapa.shared::cluster.u32 %0, %1, %2;" : "=r"(hs_peerH) : "r"(hl_), "r"(rk^1u));
      uint32_t ll_ = s0 + Q2_HSL;
      asm("mapa.shared::cluster.u32 %0, %1, %2;" : "=r"(hs_peerL) : "r"(ll_), "r"(rk^1u)); }

    asm volatile("barrier.cluster.arrive.aligned;" ::: "memory");
    asm volatile("barrier.cluster.wait.aligned;" ::: "memory");

    // prefetch xg[0] (own rows) into buf 0
    #pragma unroll
    for (int k = 0; k < 4; k++){
        int idx = tid + 384*k;                     // < 1536 chunks
        int gx = idx / 512, rem = idx & 511;
        int row = rem >> 4, off = rem & 15;
        cpa16(smf + XGSf + gx*2048 + row*64 + off*4,
              xg + ((size_t)((0*3 + gx)*NB + n))*4096 + (A0+row)*64 + off*4);
    }
    asm volatile("cp.async.commit_group;");

    int buf = 0;
    for (int t = 0; t < LS; t++){
        if (t + 1 < LS){
            #pragma unroll
            for (int k = 0; k < 4; k++){
                int idx = tid + 384*k;
                int gx = idx / 512, rem = idx & 511;
                int row = rem >> 4, off = rem & 15;
                cpa16(smf + XGSf + (buf^1)*6144 + gx*2048 + row*64 + off*4,
                      xg + ((size_t)(((t+1)*3 + gx)*NB + n))*4096 + (A0+row)*64 + off*4);
            }
        }
        asm volatile("cp.async.commit_group;");

        // ---- stage1: T[16 rows, j in jh-half] = Wu1[g,own rows] @ h ----
        float D[4][4];
        #pragma unroll
        for (int q = 0; q < 4; q++){ D[q][0]=D[q][1]=D[q][2]=D[q][3]=0.0f; }
        #pragma unroll
        for (int kc = 0; kc < 4; kc++){
            #pragma unroll
            for (int nb = 0; nb < 2; nb++){
                uint32_t Bh[4], Bl[4];
                ldm4t(Bh, fraddr(s0 + Q2_HSH, kc*16, (jh*2+nb)*16, lane));
                ldm4t(Bl, fraddr(s0 + Q2_HSL, kc*16, (jh*2+nb)*16, lane));
                mma16816(D[2*nb],   Ah[kc], Bh[0], Bh[1]);
                mma16816(D[2*nb+1], Ah[kc], Bh[2], Bh[3]);
                mma16816(D[2*nb],   Ah[kc], Bl[0], Bl[1]);
                mma16816(D[2*nb+1], Ah[kc], Bl[2], Bl[3]);
                mma16816(D[2*nb],   Al[kc], Bh[0], Bh[1]);
                mma16816(D[2*nb+1], Al[kc], Bh[2], Bh[3]);
            }
        }
        // ---- repack D -> A2 fragments (2 local k-chunks) ----
        uint32_t A2h[2][4], A2l[2][4];
        #pragma unroll
        for (int c = 0; c < 2; c++){
            uint2 p0 = split2(D[2*c][0],   D[2*c][1]);
            uint2 p1 = split2(D[2*c][2],   D[2*c][3]);
            uint2 p2 = split2(D[2*c+1][0], D[2*c+1][1]);
            uint2 p3 = split2(D[2*c+1][2], D[2*c+1][3]);
            A2h[c][0]=p0.x; A2h[c][1]=p1.x; A2h[c][2]=p2.x; A2h[c][3]=p3.x;
            A2l[c][0]=p0.y; A2l[c][1]=p1.y; A2l[c][2]=p2.y; A2l[c][3]=p3.y;
        }
        // ---- stage2 partial: E = T[.., jh-half] @ Wu2t[jh-half rows, all b] ----
        float E[8][4];
        #pragma unroll
        for (int q = 0; q < 8; q++){ E[q][0]=E[q][1]=E[q][2]=E[q][3]=0.0f; }
        #pragma unroll
        for (int c = 0; c < 2; c++){
            #pragma unroll
            for (int nb = 0; nb < 4; nb++){
                uint32_t Bh[4], Bl[4];
                ldm4t(Bh, fraddr(w2hB, jh*32 + c*16, nb*16, lane));
                ldm4t(Bl, fraddr(w2lB, jh*32 + c*16, nb*16, lane));
                mma16816(E[2*nb],   A2h[c], Bh[0], Bh[1]);
                mma16816(E[2*nb+1], A2h[c], Bh[2], Bh[3]);
                mma16816(E[2*nb],   A2h[c], Bl[0], Bl[1]);
                mma16816(E[2*nb+1], A2h[c], Bl[2], Bl[3]);
                mma16816(E[2*nb],   A2l[c], Bh[0], Bh[1]);
                mma16816(E[2*nb+1], A2l[c], Bh[2], Bh[3]);
            }
        }
        // ---- store E partial ----
        {
            float* dst = smf + EPf + (jh*3 + g)*2048;
            const int r0 = rb*16 + (lane >> 2);
            const int cb = (lane & 3) * 2;
            #pragma unroll
            for (int nb = 0; nb < 4; nb++){
                #pragma unroll
                for (int hf = 0; hf < 2; hf++){
                    int q = 2*nb + hf;
                    int b = nb*16 + hf*8 + cb;
                    float* d2 = dst + r0*64 + b;
                    *(float2*)d2          = make_float2(E[q][0], E[q][1]);
                    *(float2*)(d2 + 8*64) = make_float2(E[q][2], E[q][3]);
                }
            }
        }
        asm volatile("barrier.cluster.arrive.aligned;" ::: "memory");  // my hs reads done
        __syncthreads();                                               // E visible
        asm volatile("cp.async.wait_group 1;");
        asm volatile("barrier.cluster.wait.aligned;" ::: "memory");    // peer hs reads done

        // ---- epilogue: 256 threads, own 32 rows ----
        if (tid < 256){
            const int xb = XGSf + buf*6144;
            const int be = e_r*64 + e_c;
            float hv[8];
            #pragma unroll
            for (int k = 0; k < 8; k++){
                float z = sigm(smf[EPf + be + k] + smf[EPf + 6144 + be + k]
                               + smf[xb + be + k]);
                float r = sigm(smf[EPf + 2048 + be + k] + smf[EPf + 8192 + be + k]
                               + smf[xb + 2048 + be + k]);
                float o = sigm(smf[EPf + 4096 + be + k] + smf[EPf + 10240 + be + k]
                               + smf[xb + 4096 + be + k]);
                cst[k] = r * (cst[k] + z);
                hv[k] = o * sigm(cst[k]);
            }
            float* od = out + ((size_t)(n*LS + t))*4096 + (A0 + e_r)*64 + e_c;
            *(float4*)(od)   = make_float4(hv[0],hv[1],hv[2],hv[3]);
            *(float4*)(od+4) = make_float4(hv[4],hv[5],hv[6],hv[7]);
            if (t == LS-1){
                float* hl2 = out + (size_t)NB*LS*4096 + (size_t)n*4096 + (A0 + e_r)*64 + e_c;
                *(float4*)(hl2)   = make_float4(hv[0],hv[1],hv[2],hv[3]);
                *(float4*)(hl2+4) = make_float4(hv[4],hv[5],hv[6],hv[7]);
            }
            // split h -> hi/lo u32 packs
            uint32_t hi[4], lo[4];
            #pragma unroll
            for (int k = 0; k < 4; k++){
                uint2 hl = split2(hv[2*k], hv[2*k+1]);
                hi[k] = hl.x; lo[k] = hl.y;
            }
            uint32_t ho = (uint32_t)(((A0 + e_r)*72 + e_c) * 2);
            *(uint4*)(sb + Q2_HSH + ho) = make_uint4(hi[0],hi[1],hi[2],hi[3]);
            *(uint4*)(sb + Q2_HSL + ho) = make_uint4(lo[0],lo[1],lo[2],lo[3]);
            // peer stores (b64 x2 each)
            uint64_t h01, h23, l01, l23;
            asm("mov.b64 %0, {%1,%2};" : "=l"(h01) : "r"(hi[0]), "r"(hi[1]));
            asm("mov.b64 %0, {%1,%2};" : "=l"(h23) : "r"(hi[2]), "r"(hi[3]));
            asm("mov.b64 %0, {%1,%2};" : "=l"(l01) : "r"(lo[0]), "r"(lo[1]));
            asm("mov.b64 %0, {%1,%2};" : "=l"(l23) : "r"(lo[2]), "r"(lo[3]));
            asm volatile("st.shared::cluster.b64 [%0], %1;" :: "r"(hs_peerH + ho),     "l"(h01));
            asm volatile("st.shared::cluster.b64 [%0], %1;" :: "r"(hs_peerH + ho + 8), "l"(h23));
            asm volatile("st.shared::cluster.b64 [%0], %1;" :: "r"(hs_peerL + ho),     "l"(l01));
            asm volatile("st.shared::cluster.b64 [%0], %1;" :: "r"(hs_peerL + ho + 8), "l"(l23));
        }
        asm volatile("barrier.cluster.arrive.aligned;" ::: "memory");
        asm volatile("barrier.cluster.wait.aligned;" ::: "memory");
        buf ^= 1;
    }

    // c_last (own rows)
    if (tid < 256){
        float* cl = out + (size_t)NB*LS*4096 + (size_t)NB*4096
                        + (size_t)n*4096 + (A0 + e_r)*64 + e_c;
        *(float4*)(cl)   = make_float4(cst[0],cst[1],cst[2],cst[3]);
        *(float4*)(cl+4) = make_float4(cst[4],cst[5],cst[6],cst[7]);
    }
}

// ---------------------------------------------------------------------------
extern "C" void kernel_launch(void* const* d_in, const int* in_sizes, int n_in,
                              void* d_out, int out_size)
{
    const float* x   = (const float*)d_in[0];
    const float* Ww1 = (const float*)d_in[1];
    const float* Ww2 = (const float*)d_in[2];
    const float* Wu1 = (const float*)d_in[3];
    const float* Wu2 = (const float*)d_in[4];
    float* out = (float*)d_out;

    float* xg = nullptr;
    cudaGetSymbolAddress((void**)&xg, g_xg);

    cudaFuncSetAttribute(phase1_mma, cudaFuncAttributeMaxDynamicSharedMemorySize, (int)P1_BYTES);
    cudaFuncSetAttribute(phase2_mma, cudaFuncAttributeMaxDynamicSharedMemorySize, (int)Q2_BYTES);

    phase1_mma<<<148, 384, P1_BYTES>>>(x, Ww1, Ww2, xg);
    phase2_mma<<<2 * NB, 384, Q2_BYTES>>>(Wu1, Wu2, xg, out);
}

// round 9
// speedup vs baseline: 3.8877x; 1.0146x over previous
#include <cuda_runtime.h>
#include <cuda_bf16.h>
#include <cstdint>
#include <cstddef>

#define NB 64
#define LS 128

__device__ float g_xg[(size_t)LS*3*NB*4096];

__device__ __forceinline__ float sigm(float x){ return 1.0f/(1.0f+__expf(-x)); }
__device__ __forceinline__ void cpa16(void* dst, const float* src){
    asm volatile("cp.async.ca.shared.global [%0], [%1], 16;"
                 :: "r"((uint32_t)__cvta_generic_to_shared(dst)), "l"(src)); }
__device__ __forceinline__ uint32_t smem_u32(const void* p){
    uint32_t a; asm("{ .reg .u64 t; cvta.to.shared.u64 t, %1; cvt.u32.u64 %0, t; }"
                    : "=r"(a) : "l"(p)); return a; }

// split pair (f0,f1) -> hi bf16x2, lo-residual bf16x2
__device__ __forceinline__ uint2 split2(float f0, float f1){
    __nv_bfloat162 h2 = __floats2bfloat162_rn(f0, f1);
    uint32_t u = *(uint32_t*)&h2;
    float b0 = __uint_as_float(u << 16);
    float b1 = __uint_as_float(u & 0xffff0000u);
    __nv_bfloat162 l2 = __floats2bfloat162_rn(f0 - b0, f1 - b1);
    uint2 r; r.x = u; r.y = *(uint32_t*)&l2;
    return r;
}
__device__ __forceinline__ void ldm4(uint32_t* r, uint32_t addr){
    asm volatile("ldmatrix.sync.aligned.m8n8.x4.shared.b16 {%0,%1,%2,%3}, [%4];"
        : "=r"(r[0]),"=r"(r[1]),"=r"(r[2]),"=r"(r[3]) : "r"(addr));
}
__device__ __forceinline__ void ldm4t(uint32_t* r, uint32_t addr){
    asm volatile("ldmatrix.sync.aligned.m8n8.x4.trans.shared.b16 {%0,%1,%2,%3}, [%4];"
        : "=r"(r[0]),"=r"(r[1]),"=r"(r[2]),"=r"(r[3]) : "r"(addr));
}
__device__ __forceinline__ void mma16816(float* d, const uint32_t* a, uint32_t b0, uint32_t b1){
    asm volatile("mma.sync.aligned.m16n8k16.row.col.f32.bf16.bf16.f32 "
        "{%0,%1,%2,%3}, {%4,%5,%6,%7}, {%8,%9}, {%0,%1,%2,%3};"
        : "+f"(d[0]),"+f"(d[1]),"+f"(d[2]),"+f"(d[3])
        : "r"(a[0]),"r"(a[1]),"r"(a[2]),"r"(a[3]), "r"(b0),"r"(b1));
}
// lane address into 16x16 block of row-major bf16 array, row stride 72 elems
__device__ __forceinline__ uint32_t fraddr(uint32_t base, int row0, int col0, int lane){
    int grp = lane >> 3, lr = lane & 7;
    int row = row0 + lr + (grp & 1) * 8;
    int col = col0 + (grp >> 1) * 8;
    return base + (uint32_t)(row * 72 + col) * 2u;
}

// ===================== Phase 1 (unchanged, verified round 6) =====================
#define P1_XH   0u
#define P1_XL   9216u
#define P1_W1H  18432u
#define P1_W1L  46080u
#define P1_W2H  73728u
#define P1_W2L  101376u
#define P1_BYTES 129024u

__global__ void __launch_bounds__(384,1) phase1_mma(
    const float* __restrict__ x, const float* __restrict__ Ww1,
    const float* __restrict__ Ww2, float* __restrict__ xg)
{
    extern __shared__ char sb[];
    const uint32_t s0 = smem_u32(sb);
    const int tid = threadIdx.x, wid = tid >> 5, lane = tid & 31;

    if (tid < 192){
        const int g = tid >> 6, row = tid & 63;
        float w[64];
        #pragma unroll
        for (int q = 0; q < 16; q++)
            ((float4*)w)[q] = ((const float4*)(Ww1 + tid * 64))[q];
        uint32_t eb = (uint32_t)(g * 4608 + row * 72);
        #pragma unroll
        for (int k = 0; k < 32; k++){
            uint2 hl = split2(w[2*k], w[2*k+1]);
            *(uint32_t*)(sb + P1_W1H + (eb + 2*k)*2) = hl.x;
            *(uint32_t*)(sb + P1_W1L + (eb + 2*k)*2) = hl.y;
        }
        #pragma unroll 4
        for (int b = 0; b < 64; b++) w[b] = Ww2[g * 4096 + b * 64 + row];
        #pragma unroll
        for (int k = 0; k < 32; k++){
            uint2 hl = split2(w[2*k], w[2*k+1]);
            *(uint32_t*)(sb + P1_W2H + (eb + 2*k)*2) = hl.x;
            *(uint32_t*)(sb + P1_W2L + (eb + 2*k)*2) = hl.y;
        }
    }

    const int g  = wid >> 2;
    const int rb = wid & 3;
    const uint32_t w1hB = s0 + P1_W1H + (uint32_t)g * 9216u;
    const uint32_t w1lB = s0 + P1_W1L + (uint32_t)g * 9216u;
    const uint32_t w2hB = s0 + P1_W2H + (uint32_t)g * 9216u;
    const uint32_t w2lB = s0 + P1_W2L + (uint32_t)g * 9216u;

    float4 xr[4];
    const int xi = tid >> 2, xj = (tid & 3) * 16;

    int p = blockIdx.x;
    if (p < NB*LS && tid < 256){
        const float4* s = (const float4*)(x + (size_t)p*4096 + xi*64 + xj);
        xr[0]=s[0]; xr[1]=s[1]; xr[2]=s[2]; xr[3]=s[3];
    }

    for (; p < NB*LS; p += gridDim.x){
        __syncthreads();
        if (tid < 256){
            const float* xf = (const float*)xr;
            uint32_t eb = (uint32_t)(xi * 72 + xj);
            #pragma unroll
            for (int k = 0; k < 8; k++){
                uint2 hl = split2(xf[2*k], xf[2*k+1]);
                *(uint32_t*)(sb + P1_XH + (eb + 2*k)*2) = hl.x;
                *(uint32_t*)(sb + P1_XL + (eb + 2*k)*2) = hl.y;
            }
        }
        __syncthreads();
        int pn = p + gridDim.x;
        if (pn < NB*LS && tid < 256){
            const float4* s = (const float4*)(x + (size_t)pn*4096 + xi*64 + xj);
            xr[0]=s[0]; xr[1]=s[1]; xr[2]=s[2]; xr[3]=s[3];
        }

        float D[8][4];
        #pragma unroll
        for (int t = 0; t < 8; t++){ D[t][0]=D[t][1]=D[t][2]=D[t][3]=0.0f; }
        #pragma unroll
        for (int kc = 0; kc < 4; kc++){
            uint32_t Ah[4], Al[4];
            ldm4(Ah, fraddr(w1hB, rb*16, kc*16, lane));
            ldm4(Al, fraddr(w1lB, rb*16, kc*16, lane));
            #pragma unroll
            for (int nb = 0; nb < 4; nb++){
                uint32_t Bh[4], Bl[4];
                ldm4t(Bh, fraddr(s0 + P1_XH, kc*16, nb*16, lane));
                ldm4t(Bl, fraddr(s0 + P1_XL, kc*16, nb*16, lane));
                mma16816(D[2*nb],   Ah, Bh[0], Bh[1]);
                mma16816(D[2*nb+1], Ah, Bh[2], Bh[3]);
                mma16816(D[2*nb],   Ah, Bl[0], Bl[1]);
                mma16816(D[2*nb+1], Ah, Bl[2], Bl[3]);
                mma16816(D[2*nb],   Al, Bh[0], Bh[1]);
                mma16816(D[2*nb+1], Al, Bh[2], Bh[3]);
            }
        }

        uint32_t A2h[4][4], A2l[4][4];
        #pragma unroll
        for (int kc = 0; kc < 4; kc++){
            uint2 p0 = split2(D[2*kc][0],   D[2*kc][1]);
            uint2 p1 = split2(D[2*kc][2],   D[2*kc][3]);
            uint2 p2 = split2(D[2*kc+1][0], D[2*kc+1][1]);
            uint2 p3 = split2(D[2*kc+1][2], D[2*kc+1][3]);
            A2h[kc][0]=p0.x; A2h[kc][1]=p1.x; A2h[kc][2]=p2.x; A2h[kc][3]=p3.x;
            A2l[kc][0]=p0.y; A2l[kc][1]=p1.y; A2l[kc][2]=p2.y; A2l[kc][3]=p3.y;
        }

        float E[8][4];
        #pragma unroll
        for (int t = 0; t < 8; t++){ E[t][0]=E[t][1]=E[t][2]=E[t][3]=0.0f; }
        #pragma unroll
        for (int kc = 0; kc < 4; kc++){
            #pragma unroll
            for (int nb = 0; nb < 4; nb++){
                uint32_t Bh[4], Bl[4];
                ldm4t(Bh, fraddr(w2hB, kc*16, nb*16, lane));
                ldm4t(Bl, fraddr(w2lB, kc*16, nb*16, lane));
                mma16816(E[2*nb],   A2h[kc], Bh[0], Bh[1]);
                mma16816(E[2*nb+1], A2h[kc], Bh[2], Bh[3]);
                mma16816(E[2*nb],   A2h[kc], Bl[0], Bl[1]);
                mma16816(E[2*nb+1], A2h[kc], Bl[2], Bl[3]);
                mma16816(E[2*nb],   A2l[kc], Bh[0], Bh[1]);
                mma16816(E[2*nb+1], A2l[kc], Bh[2], Bh[3]);
            }
        }

        {
            const int n = p >> 7, l = p & 127;
            float* dst = xg + ((size_t)((l*3+g)*NB + n))*4096;
            const int r0 = rb*16 + (lane >> 2);
            const int cb = (lane & 3) * 2;
            #pragma unroll
            for (int nb = 0; nb < 4; nb++){
                #pragma unroll
                for (int hf = 0; hf < 2; hf++){
                    int t = 2*nb + hf;
                    int b = nb*16 + hf*8 + cb;
                    float* q = dst + r0*64 + b;
                    *(float2*)q          = make_float2(E[t][0], E[t][1]);
                    *(float2*)(q + 8*64) = make_float2(E[t][2], E[t][3]);
                }
            }
        }
    }
}

// ===================== Phase 2 (mma.sync, cluster-2, double-buffered h) =====================
// h buffers: HB0 at 0, HB1 at 18432 (each: hi 9216 + lo 9216)
// W2H 36864 (27648) | W2L 64512 (27648) | EP 92160 (49152) | XGS 141312 (2x24576)
#define R2_W2H 36864u
#define R2_W2L 64512u
#define R2_EP  92160u
#define R2_XGS 141312u
#define R2_BYTES 190464u

__global__ void __launch_bounds__(384,1) __cluster_dims__(2,1,1) phase2_mma(
    const float* __restrict__ Wu1, const float* __restrict__ Wu2,
    const float* __restrict__ xg, float* __restrict__ out)
{
    extern __shared__ char sb[];
    const uint32_t s0 = smem_u32(sb);
    float* smf = (float*)sb;
    const int tid = threadIdx.x, wid = tid >> 5, lane = tid & 31;
    uint32_t rk; asm("mov.u32 %0, %%cluster_ctarank;" : "=r"(rk));
    const int n  = blockIdx.x >> 1;
    const int A0 = (int)rk * 32;
    const int EPf = 23040, XGSf = 35328;     // float indices

    // ---- init: Wu2t split (full, both CTAs) ----
    if (tid < 192){
        const int g = tid >> 6, j = tid & 63;
        float w[64];
        #pragma unroll 4
        for (int b = 0; b < 64; b++) w[b] = Wu2[g*4096 + b*64 + j];
        uint32_t eb = (uint32_t)((g*64 + j) * 72);
        #pragma unroll
        for (int k = 0; k < 32; k++){
            uint2 hl = split2(w[2*k], w[2*k+1]);
            *(uint32_t*)(sb + R2_W2H + (eb + 2*k)*2) = hl.x;
            *(uint32_t*)(sb + R2_W2L + (eb + 2*k)*2) = hl.y;
        }
    }
    // ---- Wu1 own 32 rows per gate, split into temp (XGS area) ----
    if (tid < 96){
        const int g = tid >> 5, a = tid & 31;
        float w[64];
        #pragma unroll
        for (int q = 0; q < 16; q++)
            ((float4*)w)[q] = ((const float4*)(Wu1 + (size_t)(g*64 + A0 + a)*64))[q];
        uint32_t eb = (uint32_t)((g*32 + a) * 72);
        #pragma unroll
        for (int k = 0; k < 32; k++){
            uint2 hl = split2(w[2*k], w[2*k+1]);
            *(uint32_t*)(sb + R2_XGS + (eb + 2*k)*2) = hl.x;
            *(uint32_t*)(sb + R2_XGS + 13824u + (eb + 2*k)*2) = hl.y;
        }
    }
    // zero both h buffers (2 x 18432 B)
    for (int i = tid; i < 9216; i += 384) ((uint32_t*)sb)[i] = 0;
    __syncthreads();

    // ---- warp task + A-fragment preload (constant over t) ----
    const int g  = wid >> 2;          // 0..2
    const int rb = (wid >> 1) & 1;    // rowblock16 within own 32 rows
    const int jh = wid & 1;           // j half
    uint32_t Ah[4][4], Al[4][4];
    #pragma unroll
    for (int kc = 0; kc < 4; kc++){
        ldm4(Ah[kc], fraddr(s0 + R2_XGS + (uint32_t)g*4608u, rb*16, kc*16, lane));
        ldm4(Al[kc], fraddr(s0 + R2_XGS + 13824u + (uint32_t)g*4608u, rb*16, kc*16, lane));
    }
    __syncthreads();   // temp reads done; XGS reusable

    const uint32_t w2hB = s0 + R2_W2H + (uint32_t)g * 9216u;
    const uint32_t w2lB = s0 + R2_W2L + (uint32_t)g * 9216u;

    // epilogue mapping: 256 threads, 8 cols each over own 32 rows
    const int e_r = tid >> 3, e_c = (tid & 7) * 8;
    float cst[8];
    #pragma unroll
    for (int k = 0; k < 8; k++) cst[k] = 0.0f;

    uint32_t pb;   // peer smem base
    asm("mapa.shared::cluster.u32 %0, %1, %2;" : "=r"(pb) : "r"(s0), "r"(rk^1u));

    // prefetch xg[0] (own rows) into buf 0
    #pragma unroll
    for (int k = 0; k < 4; k++){
        int idx = tid + 384*k;                     // < 1536 chunks
        int gx = idx / 512, rem = idx & 511;
        int row = rem >> 4, off = rem & 15;
        cpa16(smf + XGSf + gx*2048 + row*64 + off*4,
              xg + ((size_t)((0*3 + gx)*NB + n))*4096 + (A0+row)*64 + off*4);
    }
    asm volatile("cp.async.commit_group;");

    // both CTAs' h buffers zeroed before any peer store
    asm volatile("barrier.cluster.arrive.aligned;" ::: "memory");
    asm volatile("barrier.cluster.wait.aligned;" ::: "memory");

    int buf = 0, hb = 0;
    for (int t = 0; t < LS; t++){
        const uint32_t hsH = s0 + (uint32_t)hb*18432u;
        const uint32_t hsL = hsH + 9216u;

        // ---- stage1: T[16 rows, jh-half] = Wu1[g,own rows] @ h[hb] ----
        float D[4][4];
        #pragma unroll
        for (int q = 0; q < 4; q++){ D[q][0]=D[q][1]=D[q][2]=D[q][3]=0.0f; }
        #pragma unroll
        for (int kc = 0; kc < 4; kc++){
            #pragma unroll
            for (int nb = 0; nb < 2; nb++){
                uint32_t Bh[4], Bl[4];
                ldm4t(Bh, fraddr(hsH, kc*16, (jh*2+nb)*16, lane));
                ldm4t(Bl, fraddr(hsL, kc*16, (jh*2+nb)*16, lane));
                mma16816(D[2*nb],   Ah[kc], Bh[0], Bh[1]);
                mma16816(D[2*nb+1], Ah[kc], Bh[2], Bh[3]);
                mma16816(D[2*nb],   Ah[kc], Bl[0], Bl[1]);
                mma16816(D[2*nb+1], Ah[kc], Bl[2], Bl[3]);
                mma16816(D[2*nb],   Al[kc], Bh[0], Bh[1]);
                mma16816(D[2*nb+1], Al[kc], Bh[2], Bh[3]);
            }
        }
        // ---- repack D -> A2 fragments ----
        uint32_t A2h[2][4], A2l[2][4];
        #pragma unroll
        for (int c = 0; c < 2; c++){
            uint2 p0 = split2(D[2*c][0],   D[2*c][1]);
            uint2 p1 = split2(D[2*c][2],   D[2*c][3]);
            uint2 p2 = split2(D[2*c+1][0], D[2*c+1][1]);
            uint2 p3 = split2(D[2*c+1][2], D[2*c+1][3]);
            A2h[c][0]=p0.x; A2h[c][1]=p1.x; A2h[c][2]=p2.x; A2h[c][3]=p3.x;
            A2l[c][0]=p0.y; A2l[c][1]=p1.y; A2l[c][2]=p2.y; A2l[c][3]=p3.y;
        }
        // ---- stage2 partial ----
        float E[8][4];
        #pragma unroll
        for (int q = 0; q < 8; q++){ E[q][0]=E[q][1]=E[q][2]=E[q][3]=0.0f; }
        #pragma unroll
        for (int c = 0; c < 2; c++){
            #pragma unroll
            for (int nb = 0; nb < 4; nb++){
                uint32_t Bh[4], Bl[4];
                ldm4t(Bh, fraddr(w2hB, jh*32 + c*16, nb*16, lane));
                ldm4t(Bl, fraddr(w2lB, jh*32 + c*16, nb*16, lane));
                mma16816(E[2*nb],   A2h[c], Bh[0], Bh[1]);
                mma16816(E[2*nb+1], A2h[c], Bh[2], Bh[3]);
                mma16816(E[2*nb],   A2h[c], Bl[0], Bl[1]);
                mma16816(E[2*nb+1], A2h[c], Bl[2], Bl[3]);
                mma16816(E[2*nb],   A2l[c], Bh[0], Bh[1]);
                mma16816(E[2*nb+1], A2l[c], Bh[2], Bh[3]);
            }
        }
        // ---- store E partial ----
        {
            float* dst = smf + EPf + (jh*3 + g)*2048;
            const int r0 = rb*16 + (lane >> 2);
            const int cb = (lane & 3) * 2;
            #pragma unroll
            for (int nb = 0; nb < 4; nb++){
                #pragma unroll
                for (int hf = 0; hf < 2; hf++){
                    int q = 2*nb + hf;
                    int b = nb*16 + hf*8 + cb;
                    float* d2 = dst + r0*64 + b;
                    *(float2*)d2          = make_float2(E[q][0], E[q][1]);
                    *(float2*)(d2 + 8*64) = make_float2(E[q][2], E[q][3]);
                }
            }
        }
        asm volatile("cp.async.wait_group 0;");
        __syncthreads();                  // E + xg[t] visible to all

        // ---- epilogue (h -> h[hb^1], local + peer) ----
        float hv[8];
        if (tid < 256){
            const int xb = XGSf + buf*6144;
            const int be = e_r*64 + e_c;
            #pragma unroll
            for (int k = 0; k < 8; k++){
                float z = sigm(smf[EPf + be + k] + smf[EPf + 6144 + be + k]
                               + smf[xb + be + k]);
                float r = sigm(smf[EPf + 2048 + be + k] + smf[EPf + 8192 + be + k]
                               + smf[xb + 2048 + be + k]);
                float o = sigm(smf[EPf + 4096 + be + k] + smf[EPf + 10240 + be + k]
                               + smf[xb + 4096 + be + k]);
                cst[k] = r * (cst[k] + z);
                hv[k] = o * sigm(cst[k]);
            }
            uint32_t hi[4], lo[4];
            #pragma unroll
            for (int k = 0; k < 4; k++){
                uint2 hl = split2(hv[2*k], hv[2*k+1]);
                hi[k] = hl.x; lo[k] = hl.y;
            }
            const uint32_t hwb = (uint32_t)(hb^1)*18432u;
            const uint32_t ho = (uint32_t)(((A0 + e_r)*72 + e_c) * 2);
            *(uint4*)(sb + hwb + ho)         = make_uint4(hi[0],hi[1],hi[2],hi[3]);
            *(uint4*)(sb + hwb + 9216u + ho) = make_uint4(lo[0],lo[1],lo[2],lo[3]);
            uint64_t h01, h23, l01, l23;
            asm("mov.b64 %0, {%1,%2};" : "=l"(h01) : "r"(hi[0]), "r"(hi[1]));
            asm("mov.b64 %0, {%1,%2};" : "=l"(h23) : "r"(hi[2]), "r"(hi[3]));
            asm("mov.b64 %0, {%1,%2};" : "=l"(l01) : "r"(lo[0]), "r"(lo[1]));
            asm("mov.b64 %0, {%1,%2};" : "=l"(l23) : "r"(lo[2]), "r"(lo[3]));
            asm volatile("st.shared::cluster.b64 [%0], %1;" :: "r"(pb + hwb + ho),          "l"(h01));
            asm volatile("st.shared::cluster.b64 [%0], %1;" :: "r"(pb + hwb + ho + 8),      "l"(h23));
            asm volatile("st.shared::cluster.b64 [%0], %1;" :: "r"(pb + hwb + 9216u + ho),     "l"(l01));
            asm volatile("st.shared::cluster.b64 [%0], %1;" :: "r"(pb + hwb + 9216u + ho + 8), "l"(l23));
        }
        // arrive (releases the peer-h stores), then overlap STG/prefetch, then wait
        asm volatile("barrier.cluster.arrive.aligned;" ::: "memory");

        if (tid < 256){
            float* od = out + ((size_t)(n*LS + t))*4096 + (A0 + e_r)*64 + e_c;
            *(float4*)(od)   = make_float4(hv[0],hv[1],hv[2],hv[3]);
            *(float4*)(od+4) = make_float4(hv[4],hv[5],hv[6],hv[7]);
            if (t == LS-1){
                float* hl2 = out + (size_t)NB*LS*4096 + (size_t)n*4096 + (A0 + e_r)*64 + e_c;
                *(float4*)(hl2)   = make_float4(hv[0],hv[1],hv[2],hv[3]);
                *(float4*)(hl2+4) = make_float4(hv[4],hv[5],hv[6],hv[7]);
            }
        }
        if (t + 1 < LS){
            #pragma unroll
            for (int k = 0; k < 4; k++){
                int idx = tid + 384*k;
                int gx = idx / 512, rem = idx & 511;
                int row = rem >> 4, off = rem & 15;
                cpa16(smf + XGSf + (buf^1)*6144 + gx*2048 + row*64 + off*4,
                      xg + ((size_t)(((t+1)*3 + gx)*NB + n))*4096 + (A0+row)*64 + off*4);
            }
        }
        asm volatile("cp.async.commit_group;");

        asm volatile("barrier.cluster.wait.aligned;" ::: "memory");
        buf ^= 1; hb ^= 1;
    }

    // c_last (own rows)
    if (tid < 256){
        float* cl = out + (size_t)NB*LS*4096 + (size_t)NB*4096
                        + (size_t)n*4096 + (A0 + e_r)*64 + e_c;
        *(float4*)(cl)   = make_float4(cst[0],cst[1],cst[2],cst[3]);
        *(float4*)(cl+4) = make_float4(cst[4],cst[5],cst[6],cst[7]);
    }
}

// ---------------------------------------------------------------------------
extern "C" void kernel_launch(void* const* d_in, const int* in_sizes, int n_in,
                              void* d_out, int out_size)
{
    const float* x   = (const float*)d_in[0];
    const float* Ww1 = (const float*)d_in[1];
    const float* Ww2 = (const float*)d_in[2];
    const float* Wu1 = (const float*)d_in[3];
    const float* Wu2 = (const float*)d_in[4];
    float* out = (float*)d_out;

    float* xg = nullptr;
    cudaGetSymbolAddress((void**)&xg, g_xg);

    cudaFuncSetAttribute(phase1_mma, cudaFuncAttributeMaxDynamicSharedMemorySize, (int)P1_BYTES);
    cudaFuncSetAttribute(phase2_mma, cudaFuncAttributeMaxDynamicSharedMemorySize, (int)R2_BYTES);

    phase1_mma<<<148, 384, P1_BYTES>>>(x, Ww1, Ww2, xg);
    phase2_mma<<<2 * NB, 384, R2_BYTES>>>(Wu1, Wu2, xg, out);
}